// round 4
// baseline (speedup 1.0000x reference)
#include <cuda_runtime.h>
#include <cuda_bf16.h>
#include <math.h>

// Problem constants (fixed shapes from reference)
#define B_  4
#define T_  2048
#define C_  1024
#define H_  16
#define HD_ 64
#define M_ROWS (B_ * T_)          // 8192
#define QKV_N  (3 * C_)           // 3072

typedef unsigned long long ull;

// ---- packed f32x2 helpers (Blackwell sm_100+) ----
__device__ __forceinline__ ull pk2(float lo, float hi) {
    ull r; asm("mov.b64 %0, {%1, %2};" : "=l"(r) : "f"(lo), "f"(hi)); return r;
}
__device__ __forceinline__ ull dup2(float x) { return pk2(x, x); }
__device__ __forceinline__ ull fma2(ull a, ull b, ull c) {
    ull d; asm("fma.rn.f32x2 %0, %1, %2, %3;" : "=l"(d) : "l"(a), "l"(b), "l"(c)); return d;
}
__device__ __forceinline__ ull mul2(ull a, ull b) {
    ull d; asm("mul.rn.f32x2 %0, %1, %2;" : "=l"(d) : "l"(a), "l"(b)); return d;
}
__device__ __forceinline__ void upk2(ull v, float& lo, float& hi) {
    asm("mov.b64 {%0, %1}, %2;" : "=f"(lo), "=f"(hi) : "l"(v));
}

// -------- scratch (device globals; no allocation allowed) --------
__device__ float g_qkv[(size_t)M_ROWS * QKV_N];        // 96 MB (B*T, 3C)
__device__ float g_q[(size_t)B_ * H_ * T_ * HD_];      // 32 MB (B*H, T, hd) roped+scaled
__device__ float g_k[(size_t)B_ * H_ * T_ * HD_];      // 32 MB
__device__ float g_v[(size_t)B_ * H_ * T_ * HD_];      // 32 MB
__device__ float g_y[(size_t)M_ROWS * C_];             // 32 MB (B, T, C) attention output

// ============================================================================
// GEMM (NT): C[m,n] = sum_k A[m*K+k] * B[n*K+k]
// 128x128 tile, BK=16, 256 threads, 8x8 microtile as 4 packed row-pairs,
// double-buffered smem with register-staged prefetch, f32x2 FMA.
// ============================================================================
#define BM 128
#define BN 128
#define BK 16

__global__ __launch_bounds__(256, 2) void gemm_nt(
    const float* __restrict__ A, const float* __restrict__ Bm,
    float* __restrict__ C, int M, int N, int K)
{
    __shared__ float As[2][BK][BM];
    __shared__ float Bs[2][BK][BN];

    const int bm = blockIdx.y * BM;
    const int bn = blockIdx.x * BN;
    const int tid = threadIdx.x;
    const int tx = tid & 15;       // 0..15
    const int ty = tid >> 4;       // 0..15

    const int lrow = tid >> 2;         // 0..63
    const int lcol = (tid & 3) * 4;    // 0,4,8,12

    const float* Ab = A  + (size_t)(bm + lrow) * K + lcol;
    const float* Bb = Bm + (size_t)(bn + lrow) * K + lcol;
    const size_t rowK64 = (size_t)64 * K;

    // acc2[ip][j]: rows (ty*8+2ip, ty*8+2ip+1) x col (tx*8+j), packed f32x2
    ull acc2[4][8];
#pragma unroll
    for (int ip = 0; ip < 4; ++ip)
#pragma unroll
        for (int j = 0; j < 8; ++j) acc2[ip][j] = 0ull;

    // ---- load tile 0 into buffer 0 ----
    {
        float4 a0 = *(const float4*)(Ab);
        float4 a1 = *(const float4*)(Ab + rowK64);
        float4 b0 = *(const float4*)(Bb);
        float4 b1 = *(const float4*)(Bb + rowK64);
        As[0][lcol + 0][lrow] = a0.x; As[0][lcol + 1][lrow] = a0.y;
        As[0][lcol + 2][lrow] = a0.z; As[0][lcol + 3][lrow] = a0.w;
        As[0][lcol + 0][lrow + 64] = a1.x; As[0][lcol + 1][lrow + 64] = a1.y;
        As[0][lcol + 2][lrow + 64] = a1.z; As[0][lcol + 3][lrow + 64] = a1.w;
        Bs[0][lcol + 0][lrow] = b0.x; Bs[0][lcol + 1][lrow] = b0.y;
        Bs[0][lcol + 2][lrow] = b0.z; Bs[0][lcol + 3][lrow] = b0.w;
        Bs[0][lcol + 0][lrow + 64] = b1.x; Bs[0][lcol + 1][lrow + 64] = b1.y;
        Bs[0][lcol + 2][lrow + 64] = b1.z; Bs[0][lcol + 3][lrow + 64] = b1.w;
    }
    __syncthreads();

    int p = 0;
    for (int k0 = BK; k0 < K; k0 += BK) {
        // prefetch next slab into registers
        float4 na0 = *(const float4*)(Ab + k0);
        float4 na1 = *(const float4*)(Ab + k0 + rowK64);
        float4 nb0 = *(const float4*)(Bb + k0);
        float4 nb1 = *(const float4*)(Bb + k0 + rowK64);

        // compute on buffer p
#pragma unroll
        for (int kk = 0; kk < BK; ++kk) {
            ull a2[4];
#pragma unroll
            for (int ip = 0; ip < 4; ++ip)
                a2[ip] = *(const ull*)&As[p][kk][ty * 8 + 2 * ip];
            float4 b0 = *(const float4*)&Bs[p][kk][tx * 8];
            float4 b1 = *(const float4*)&Bs[p][kk][tx * 8 + 4];
            ull rb2[8] = {dup2(b0.x), dup2(b0.y), dup2(b0.z), dup2(b0.w),
                          dup2(b1.x), dup2(b1.y), dup2(b1.z), dup2(b1.w)};
#pragma unroll
            for (int ip = 0; ip < 4; ++ip)
#pragma unroll
                for (int j = 0; j < 8; ++j)
                    acc2[ip][j] = fma2(a2[ip], rb2[j], acc2[ip][j]);
        }

        // stage prefetch into the other buffer
        const int q = p ^ 1;
        As[q][lcol + 0][lrow] = na0.x; As[q][lcol + 1][lrow] = na0.y;
        As[q][lcol + 2][lrow] = na0.z; As[q][lcol + 3][lrow] = na0.w;
        As[q][lcol + 0][lrow + 64] = na1.x; As[q][lcol + 1][lrow + 64] = na1.y;
        As[q][lcol + 2][lrow + 64] = na1.z; As[q][lcol + 3][lrow + 64] = na1.w;
        Bs[q][lcol + 0][lrow] = nb0.x; Bs[q][lcol + 1][lrow] = nb0.y;
        Bs[q][lcol + 2][lrow] = nb0.z; Bs[q][lcol + 3][lrow] = nb0.w;
        Bs[q][lcol + 0][lrow + 64] = nb1.x; Bs[q][lcol + 1][lrow + 64] = nb1.y;
        Bs[q][lcol + 2][lrow + 64] = nb1.z; Bs[q][lcol + 3][lrow + 64] = nb1.w;
        __syncthreads();
        p = q;
    }

    // last slab
#pragma unroll
    for (int kk = 0; kk < BK; ++kk) {
        ull a2[4];
#pragma unroll
        for (int ip = 0; ip < 4; ++ip)
            a2[ip] = *(const ull*)&As[p][kk][ty * 8 + 2 * ip];
        float4 b0 = *(const float4*)&Bs[p][kk][tx * 8];
        float4 b1 = *(const float4*)&Bs[p][kk][tx * 8 + 4];
        ull rb2[8] = {dup2(b0.x), dup2(b0.y), dup2(b0.z), dup2(b0.w),
                      dup2(b1.x), dup2(b1.y), dup2(b1.z), dup2(b1.w)};
#pragma unroll
        for (int ip = 0; ip < 4; ++ip)
#pragma unroll
            for (int j = 0; j < 8; ++j)
                acc2[ip][j] = fma2(a2[ip], rb2[j], acc2[ip][j]);
    }

    // epilogue: unpack row pairs, store
#pragma unroll
    for (int ip = 0; ip < 4; ++ip) {
        float lo[8], hi[8];
#pragma unroll
        for (int j = 0; j < 8; ++j) upk2(acc2[ip][j], lo[j], hi[j]);
        float* c0p = C + (size_t)(bm + ty * 8 + 2 * ip) * N + bn + tx * 8;
        float* c1p = c0p + N;
        ((float4*)c0p)[0] = make_float4(lo[0], lo[1], lo[2], lo[3]);
        ((float4*)c0p)[1] = make_float4(lo[4], lo[5], lo[6], lo[7]);
        ((float4*)c1p)[0] = make_float4(hi[0], hi[1], hi[2], hi[3]);
        ((float4*)c1p)[1] = make_float4(hi[4], hi[5], hi[6], hi[7]);
    }
}

// ============================================================================
// RoPE + rearrange: qkv (B*T, 3C) -> Q/K/V (B*H, T, hd)
// ============================================================================
__global__ __launch_bounds__(256) void rope_rearrange(const float* __restrict__ qkv)
{
    int idx = blockIdx.x * blockDim.x + threadIdx.x;
    if (idx >= B_ * T_ * H_ * (HD_ / 2)) return;

    int i = idx & 31;               // pair index 0..31
    int h = (idx >> 5) & 15;
    int t = (idx >> 9) & 2047;
    int b = idx >> 20;

    const float* src = qkv + (size_t)(b * T_ + t) * QKV_N + h * HD_ + 2 * i;

    double inv = exp2(-(double)i * (13.287712379549449595 / 32.0)); // 10000^(-i/32)
    double ang = (double)t * inv;
    double ds, dc;
    sincos(ang, &ds, &dc);
    float s = (float)ds, c = (float)dc;

    float q0 = src[0],       q1 = src[1];
    float k0 = src[C_],      k1 = src[C_ + 1];
    float2 v2 = *(const float2*)(src + 2 * C_);

    size_t dst = ((size_t)(b * H_ + h) * T_ + t) * HD_ + 2 * i;
    const float qs = 0.125f;  // 1/sqrt(64)
    g_q[dst]     = (q0 * c - q1 * s) * qs;
    g_q[dst + 1] = (q0 * s + q1 * c) * qs;
    g_k[dst]     = k0 * c - k1 * s;
    g_k[dst + 1] = k0 * s + k1 * c;
    *(float2*)(g_v + dst) = v2;
}

// ============================================================================
// Flash attention (f32x2): Bq=128, Bk=64, hd=64. 256 threads (16x16),
// 8x4 microtile. QK packed along rows, PV/O packed along cols.
// smem strides all multiples of 4 floats:
//   Qs [64][128] d-major, Ks [64][64] d-major, Vs [64][68] k-major,
//   Ps [128][68] r-major.
// ============================================================================
#define QS_STRIDE 128
#define KS_STRIDE 64
#define VS_STRIDE 68
#define PS_STRIDE 68
#define QS_OFF 0
#define KS_OFF (64 * QS_STRIDE)                 // 8192
#define VS_OFF (KS_OFF + 64 * KS_STRIDE)        // 12288
#define PS_OFF (VS_OFF + 64 * VS_STRIDE)        // 16640
#define FLASH_SMEM ((PS_OFF + 128 * PS_STRIDE) * 4)  // 101376 bytes

__global__ __launch_bounds__(256, 2) void flash_attn()
{
    extern __shared__ float smem[];
    float* Qs = smem + QS_OFF;
    float* Ks = smem + KS_OFF;
    float* Vs = smem + VS_OFF;
    float* Ps = smem + PS_OFF;

    const int bh = blockIdx.y;                // 0..63
    const int b  = bh >> 4;
    const int h  = bh & 15;
    const int q0 = blockIdx.x * 128;

    const float* Qb = g_q + (size_t)bh * T_ * HD_;
    const float* Kb = g_k + (size_t)bh * T_ * HD_;
    const float* Vb = g_v + (size_t)bh * T_ * HD_;

    const int tid = threadIdx.x;
    const int tx = tid & 15;
    const int ty = tid >> 4;
    const int r0 = ty * 8;
    const int c0 = tx * 4;

    // Q loader: each thread loads row lrQ, 32 d-values (8 float4), transposed store
    const int lrQ = tid >> 1;
    const int lcQ = (tid & 1) * 32;
#pragma unroll
    for (int pQ = 0; pQ < 8; ++pQ) {
        int d = lcQ + pQ * 4;
        float4 v = *(const float4*)(Qb + (size_t)(q0 + lrQ) * HD_ + d);
        Qs[(d + 0) * QS_STRIDE + lrQ] = v.x;
        Qs[(d + 1) * QS_STRIDE + lrQ] = v.y;
        Qs[(d + 2) * QS_STRIDE + lrQ] = v.z;
        Qs[(d + 3) * QS_STRIDE + lrQ] = v.w;
    }

    // K/V loader: lr = tid>>2 (0..63), lc = (tid&3)*16
    const int lr = tid >> 2;
    const int lc = (tid & 3) * 16;

    // O2[i][jp]: row r0+i, cols (c0+2jp, c0+2jp+1) packed
    ull O2[8][2];
    float m[8], l[8];
#pragma unroll
    for (int i = 0; i < 8; ++i) {
        m[i] = -3.0e38f; l[i] = 0.0f;
        O2[i][0] = 0ull; O2[i][1] = 0ull;
    }

    for (int kt = 0; kt < T_ / 64; ++kt) {
        const int k0 = kt * 64;
        __syncthreads();   // previous tile's readers done (also covers Qs stores)
#pragma unroll
        for (int pp = 0; pp < 4; ++pp) {
            int d = lc + pp * 4;
            float4 kv = *(const float4*)(Kb + (size_t)(k0 + lr) * HD_ + d);
            Ks[(d + 0) * KS_STRIDE + lr] = kv.x;
            Ks[(d + 1) * KS_STRIDE + lr] = kv.y;
            Ks[(d + 2) * KS_STRIDE + lr] = kv.z;
            Ks[(d + 3) * KS_STRIDE + lr] = kv.w;
            float4 vv = *(const float4*)(Vb + (size_t)(k0 + lr) * HD_ + d);
            *(float4*)(Vs + lr * VS_STRIDE + d) = vv;
        }
        __syncthreads();

        // S = Q K^T (scale folded into Q); packed along rows
        ull s2[4][4];
#pragma unroll
        for (int ip = 0; ip < 4; ++ip)
#pragma unroll
            for (int j = 0; j < 4; ++j) s2[ip][j] = 0ull;

#pragma unroll 4
        for (int d = 0; d < 64; ++d) {
            ull a2[4];
#pragma unroll
            for (int ip = 0; ip < 4; ++ip)
                a2[ip] = *(const ull*)(Qs + d * QS_STRIDE + r0 + 2 * ip);
            float4 b4 = *(const float4*)(Ks + d * KS_STRIDE + c0);
            ull rb2[4] = {dup2(b4.x), dup2(b4.y), dup2(b4.z), dup2(b4.w)};
#pragma unroll
            for (int ip = 0; ip < 4; ++ip)
#pragma unroll
                for (int j = 0; j < 4; ++j)
                    s2[ip][j] = fma2(a2[ip], rb2[j], s2[ip][j]);
        }

        // unpack S
        float acc[8][4];
#pragma unroll
        for (int ip = 0; ip < 4; ++ip)
#pragma unroll
            for (int j = 0; j < 4; ++j)
                upk2(s2[ip][j], acc[2 * ip][j], acc[2 * ip + 1][j]);

        // online softmax (rows shared by 16 tx-lanes within half-warp)
#pragma unroll
        for (int i = 0; i < 8; ++i) {
            float mt = fmaxf(fmaxf(acc[i][0], acc[i][1]), fmaxf(acc[i][2], acc[i][3]));
#pragma unroll
            for (int off = 1; off < 16; off <<= 1)
                mt = fmaxf(mt, __shfl_xor_sync(0xffffffffu, mt, off));
            float mn = fmaxf(m[i], mt);
            float corr = __expf(m[i] - mn);
            m[i] = mn;
            l[i] *= corr;
            ull c2 = dup2(corr);
            O2[i][0] = mul2(O2[i][0], c2);
            O2[i][1] = mul2(O2[i][1], c2);

            float rs = 0.0f;
#pragma unroll
            for (int j = 0; j < 4; ++j) {
                float pv = __expf(acc[i][j] - mn);
                acc[i][j] = pv;
                rs += pv;
            }
#pragma unroll
            for (int off = 1; off < 16; off <<= 1)
                rs += __shfl_xor_sync(0xffffffffu, rs, off);
            l[i] += rs;
        }

        // store P row-major: Ps[r][k]
#pragma unroll
        for (int i = 0; i < 8; ++i)
            *(float4*)(Ps + (r0 + i) * PS_STRIDE + c0) =
                make_float4(acc[i][0], acc[i][1], acc[i][2], acc[i][3]);
        __syncthreads();

        // O += P @ V : k in blocks of 4; V pairs loaded directly (ulonglong2)
#pragma unroll 2
        for (int kk4 = 0; kk4 < 16; ++kk4) {
            const int kk = kk4 * 4;
            ulonglong2 v0 = *(const ulonglong2*)(Vs + (kk + 0) * VS_STRIDE + c0);
            ulonglong2 v1 = *(const ulonglong2*)(Vs + (kk + 1) * VS_STRIDE + c0);
            ulonglong2 v2 = *(const ulonglong2*)(Vs + (kk + 2) * VS_STRIDE + c0);
            ulonglong2 v3 = *(const ulonglong2*)(Vs + (kk + 3) * VS_STRIDE + c0);
#pragma unroll
            for (int i = 0; i < 8; ++i) {
                float4 pv = *(const float4*)(Ps + (r0 + i) * PS_STRIDE + kk);
                ull p0 = dup2(pv.x), p1 = dup2(pv.y), p2 = dup2(pv.z), p3 = dup2(pv.w);
                O2[i][0] = fma2(p0, v0.x, O2[i][0]);
                O2[i][1] = fma2(p0, v0.y, O2[i][1]);
                O2[i][0] = fma2(p1, v1.x, O2[i][0]);
                O2[i][1] = fma2(p1, v1.y, O2[i][1]);
                O2[i][0] = fma2(p2, v2.x, O2[i][0]);
                O2[i][1] = fma2(p2, v2.y, O2[i][1]);
                O2[i][0] = fma2(p3, v3.x, O2[i][0]);
                O2[i][1] = fma2(p3, v3.y, O2[i][1]);
            }
        }
    }

    // epilogue: normalize, write to (B, T, C)
#pragma unroll
    for (int i = 0; i < 8; ++i) {
        float rl = 1.0f / l[i];
        float o0, o1, o2, o3;
        upk2(O2[i][0], o0, o1);
        upk2(O2[i][1], o2, o3);
        float4 o = make_float4(o0 * rl, o1 * rl, o2 * rl, o3 * rl);
        *(float4*)(g_y + (size_t)(b * T_ + q0 + r0 + i) * C_ + h * HD_ + c0) = o;
    }
}

// ============================================================================
// launch
// ============================================================================
extern "C" void kernel_launch(void* const* d_in, const int* in_sizes, int n_in,
                              void* d_out, int out_size)
{
    const float* x      = (const float*)d_in[0];
    const float* w_attn = (const float*)d_in[1];
    const float* w_proj = (const float*)d_in[2];
    float* out = (float*)d_out;

    float* qkv_ptr; cudaGetSymbolAddress((void**)&qkv_ptr, g_qkv);
    float* y_ptr;   cudaGetSymbolAddress((void**)&y_ptr,   g_y);

    cudaFuncSetAttribute(flash_attn, cudaFuncAttributeMaxDynamicSharedMemorySize, FLASH_SMEM);

    // 1) QKV = x @ w_attn^T : (8192, 3072)
    gemm_nt<<<dim3(QKV_N / BN, M_ROWS / BM), 256>>>(x, w_attn, qkv_ptr, M_ROWS, QKV_N, C_);

    // 2) RoPE + rearrange
    {
        int n = B_ * T_ * H_ * (HD_ / 2);
        rope_rearrange<<<(n + 255) / 256, 256>>>(qkv_ptr);
    }

    // 3) flash attention -> g_y (B,T,C)
    flash_attn<<<dim3(T_ / 128, B_ * H_), 256, FLASH_SMEM>>>();

    // 4) out = y @ w_proj^T : (8192, 1024)
    gemm_nt<<<dim3(C_ / BN, M_ROWS / BM), 256>>>(y_ptr, w_proj, out, M_ROWS, C_, C_);
}

// round 6
// speedup vs baseline: 1.3886x; 1.3886x over previous
#include <cuda_runtime.h>
#include <cuda_bf16.h>
#include <math.h>
#include <cstdint>

// Problem constants (fixed shapes from reference)
#define B_  4
#define T_  2048
#define C_  1024
#define H_  16
#define HD_ 64
#define M_ROWS (B_ * T_)          // 8192
#define QKV_N  (3 * C_)           // 3072

typedef unsigned long long ull;

// -------- scratch (device globals; no allocation allowed) --------
__device__ float g_qkv[(size_t)M_ROWS * QKV_N];        // 96 MB (B*T, 3C)
__device__ float g_q[(size_t)B_ * H_ * T_ * HD_];      // 32 MB (B*H, T, hd) roped+scaled
__device__ float g_k[(size_t)B_ * H_ * T_ * HD_];      // 32 MB
__device__ float g_v[(size_t)B_ * H_ * T_ * HD_];      // 32 MB
__device__ float g_y[(size_t)M_ROWS * C_];             // 32 MB (B, T, C) attention output

// ---- tf32 helpers ----
__device__ __forceinline__ uint32_t f2tf32(float x) {
    uint32_t r; asm("cvt.rna.tf32.f32 %0, %1;" : "=r"(r) : "f"(x)); return r;
}
// D = A(16x8, tf32 row) * B(8x8, tf32 col) + D, fp32 accum
__device__ __forceinline__ void mma16n8k8(float c[4], const uint32_t a[4], const uint32_t b[2]) {
    asm volatile(
        "mma.sync.aligned.m16n8k8.row.col.f32.tf32.tf32.f32 "
        "{%0,%1,%2,%3}, {%4,%5,%6,%7}, {%8,%9}, {%0,%1,%2,%3};"
        : "+f"(c[0]), "+f"(c[1]), "+f"(c[2]), "+f"(c[3])
        : "r"(a[0]), "r"(a[1]), "r"(a[2]), "r"(a[3]), "r"(b[0]), "r"(b[1]));
}

// ============================================================================
// Tensor-core TF32 GEMM (NT): C[m,n] = sum_k A[m*K+k] * B[n*K+k]
// CTA 128x128, BK=32, 256 threads (8 warps, 2x4), warp tile 64x32.
// Smem: XOR-swizzled 32-float rows (u' = u ^ (row&7)); double buffered,
// register-staged prefetch, one sync per K-tile. Fragments per PTX
// m16n8k8.tf32 layout; fp32 accumulators.
// ============================================================================
#define GEMM_SMEM (16384 * 4)    // 2 bufs x (A 4096 + B 4096) uint32 = 64KB

__global__ void __launch_bounds__(256) gemm_tc(
    const float* __restrict__ A, const float* __restrict__ Bm,
    float* __restrict__ C, int M, int N, int K)
{
    extern __shared__ uint32_t sm[];
    // layout: A buf0 [0,4096), A buf1 [4096,8192), B buf0 [8192,12288), B buf1 [12288,16384)

    const int tid  = threadIdx.x;
    const int lane = tid & 31;
    const int wid  = tid >> 5;
    const int wm = wid & 1;          // 0..1  (M)
    const int wn = wid >> 1;         // 0..3  (N)
    const int g = lane >> 2;         // 0..7
    const int t = lane & 3;          // 0..3
    const int bm = blockIdx.y * 128;
    const int bn = blockIdx.x * 128;

    const int lrow = tid >> 3;       // 0..31 (+p*32)
    const int lu   = tid & 7;        // 16B unit within 128B row

    float acc[4][4][4];
#pragma unroll
    for (int mt = 0; mt < 4; ++mt)
#pragma unroll
        for (int nt = 0; nt < 4; ++nt)
#pragma unroll
            for (int q = 0; q < 4; ++q) acc[mt][nt][q] = 0.0f;

    float4 ra[4], rb[4];

    auto ldg_stage = [&](int k0) {
#pragma unroll
        for (int p = 0; p < 4; ++p) {
            int row = lrow + p * 32;
            ra[p] = *(const float4*)(A  + (size_t)(bm + row) * K + k0 + lu * 4);
            rb[p] = *(const float4*)(Bm + (size_t)(bn + row) * K + k0 + lu * 4);
        }
    };
    auto sts_stage = [&](int buf) {
#pragma unroll
        for (int p = 0; p < 4; ++p) {
            int row = lrow + p * 32;
            int u = lu ^ (row & 7);
            uint4 ta = make_uint4(f2tf32(ra[p].x), f2tf32(ra[p].y), f2tf32(ra[p].z), f2tf32(ra[p].w));
            uint4 tb = make_uint4(f2tf32(rb[p].x), f2tf32(rb[p].y), f2tf32(rb[p].z), f2tf32(rb[p].w));
            *(uint4*)(sm + buf * 4096 + row * 32 + u * 4) = ta;
            *(uint4*)(sm + 8192 + buf * 4096 + row * 32 + u * 4) = tb;
        }
    };

    ldg_stage(0);
    sts_stage(0);
    __syncthreads();

    const int nk = K >> 5;
    for (int kt = 0; kt < nk; ++kt) {
        const int buf = kt & 1;
        if (kt + 1 < nk) ldg_stage((kt + 1) << 5);

        const uint32_t* Asb = sm + buf * 4096;
        const uint32_t* Bsb = sm + 8192 + buf * 4096;

#pragma unroll
        for (int c8 = 0; c8 < 4; ++c8) {
            const int u0 = (2 * c8) ^ g;   // swizzled unit for k-cols [c8*8+t]
            const int u1 = u0 ^ 1;         // for k-cols [c8*8+4+t]

            uint32_t af[4][4];
#pragma unroll
            for (int mt = 0; mt < 4; ++mt) {
                const int r0 = wm * 64 + mt * 16 + g;
                af[mt][0] = Asb[r0 * 32 + u0 * 4 + t];
                af[mt][1] = Asb[(r0 + 8) * 32 + u0 * 4 + t];
                af[mt][2] = Asb[r0 * 32 + u1 * 4 + t];
                af[mt][3] = Asb[(r0 + 8) * 32 + u1 * 4 + t];
            }
            uint32_t bf[4][2];
#pragma unroll
            for (int nt = 0; nt < 4; ++nt) {
                const int n0 = wn * 32 + nt * 8 + g;
                bf[nt][0] = Bsb[n0 * 32 + u0 * 4 + t];
                bf[nt][1] = Bsb[n0 * 32 + u1 * 4 + t];
            }
#pragma unroll
            for (int mt = 0; mt < 4; ++mt)
#pragma unroll
                for (int nt = 0; nt < 4; ++nt)
                    mma16n8k8(acc[mt][nt], af[mt], bf[nt]);
        }

        if (kt + 1 < nk) sts_stage(buf ^ 1);
        __syncthreads();
    }

    // epilogue: fragment layout c0,c1 = (row g, col 2t,2t+1); c2,c3 = row g+8
#pragma unroll
    for (int mt = 0; mt < 4; ++mt) {
        const int row = bm + wm * 64 + mt * 16 + g;
#pragma unroll
        for (int nt = 0; nt < 4; ++nt) {
            const int col = bn + wn * 32 + nt * 8 + 2 * t;
            *(float2*)(C + (size_t)row * N + col)       = make_float2(acc[mt][nt][0], acc[mt][nt][1]);
            *(float2*)(C + (size_t)(row + 8) * N + col) = make_float2(acc[mt][nt][2], acc[mt][nt][3]);
        }
    }
}

// ============================================================================
// RoPE + rearrange: qkv (B*T, 3C) -> Q/K/V (B*H, T, hd)
// ============================================================================
__global__ __launch_bounds__(256) void rope_rearrange(const float* __restrict__ qkv)
{
    int idx = blockIdx.x * blockDim.x + threadIdx.x;
    if (idx >= B_ * T_ * H_ * (HD_ / 2)) return;

    int i = idx & 31;               // pair index 0..31
    int h = (idx >> 5) & 15;
    int t = (idx >> 9) & 2047;
    int b = idx >> 20;

    const float* src = qkv + (size_t)(b * T_ + t) * QKV_N + h * HD_ + 2 * i;

    double inv = exp2(-(double)i * (13.287712379549449595 / 32.0)); // 10000^(-i/32)
    double ang = (double)t * inv;
    double ds, dc;
    sincos(ang, &ds, &dc);
    float s = (float)ds, c = (float)dc;

    float q0 = src[0],       q1 = src[1];
    float k0 = src[C_],      k1 = src[C_ + 1];
    float2 v2 = *(const float2*)(src + 2 * C_);

    size_t dst = ((size_t)(b * H_ + h) * T_ + t) * HD_ + 2 * i;
    const float qs = 0.125f;  // 1/sqrt(64)
    g_q[dst]     = (q0 * c - q1 * s) * qs;
    g_q[dst + 1] = (q0 * s + q1 * c) * qs;
    g_k[dst]     = k0 * c - k1 * s;
    g_k[dst + 1] = k0 * s + k1 * c;
    *(float2*)(g_v + dst) = v2;
}

// ============================================================================
// Flash attention (fp32 SIMT, f32x2) — unchanged from Round 4 passing version
// ============================================================================
__device__ __forceinline__ ull pk2(float lo, float hi) {
    ull r; asm("mov.b64 %0, {%1, %2};" : "=l"(r) : "f"(lo), "f"(hi)); return r;
}
__device__ __forceinline__ ull dup2(float x) { return pk2(x, x); }
__device__ __forceinline__ ull fma2(ull a, ull b, ull c) {
    ull d; asm("fma.rn.f32x2 %0, %1, %2, %3;" : "=l"(d) : "l"(a), "l"(b), "l"(c)); return d;
}
__device__ __forceinline__ ull mul2(ull a, ull b) {
    ull d; asm("mul.rn.f32x2 %0, %1, %2;" : "=l"(d) : "l"(a), "l"(b)); return d;
}
__device__ __forceinline__ void upk2(ull v, float& lo, float& hi) {
    asm("mov.b64 {%0, %1}, %2;" : "=f"(lo), "=f"(hi) : "l"(v));
}

#define QS_STRIDE 128
#define KS_STRIDE 64
#define VS_STRIDE 68
#define PS_STRIDE 68
#define QS_OFF 0
#define KS_OFF (64 * QS_STRIDE)                 // 8192
#define VS_OFF (KS_OFF + 64 * KS_STRIDE)        // 12288
#define PS_OFF (VS_OFF + 64 * VS_STRIDE)        // 16640
#define FLASH_SMEM ((PS_OFF + 128 * PS_STRIDE) * 4)  // 101376 bytes

__global__ __launch_bounds__(256, 2) void flash_attn()
{
    extern __shared__ float fsm[];
    float* Qs = fsm + QS_OFF;
    float* Ks = fsm + KS_OFF;
    float* Vs = fsm + VS_OFF;
    float* Ps = fsm + PS_OFF;

    const int bh = blockIdx.y;                // 0..63
    const int b  = bh >> 4;
    const int h  = bh & 15;
    const int q0 = blockIdx.x * 128;

    const float* Qb = g_q + (size_t)bh * T_ * HD_;
    const float* Kb = g_k + (size_t)bh * T_ * HD_;
    const float* Vb = g_v + (size_t)bh * T_ * HD_;

    const int tid = threadIdx.x;
    const int tx = tid & 15;
    const int ty = tid >> 4;
    const int r0 = ty * 8;
    const int c0 = tx * 4;

    const int lrQ = tid >> 1;
    const int lcQ = (tid & 1) * 32;
#pragma unroll
    for (int pQ = 0; pQ < 8; ++pQ) {
        int d = lcQ + pQ * 4;
        float4 v = *(const float4*)(Qb + (size_t)(q0 + lrQ) * HD_ + d);
        Qs[(d + 0) * QS_STRIDE + lrQ] = v.x;
        Qs[(d + 1) * QS_STRIDE + lrQ] = v.y;
        Qs[(d + 2) * QS_STRIDE + lrQ] = v.z;
        Qs[(d + 3) * QS_STRIDE + lrQ] = v.w;
    }

    const int lr = tid >> 2;
    const int lc = (tid & 3) * 16;

    ull O2[8][2];
    float m[8], l[8];
#pragma unroll
    for (int i = 0; i < 8; ++i) {
        m[i] = -3.0e38f; l[i] = 0.0f;
        O2[i][0] = 0ull; O2[i][1] = 0ull;
    }

    for (int kt = 0; kt < T_ / 64; ++kt) {
        const int k0 = kt * 64;
        __syncthreads();
#pragma unroll
        for (int pp = 0; pp < 4; ++pp) {
            int d = lc + pp * 4;
            float4 kv = *(const float4*)(Kb + (size_t)(k0 + lr) * HD_ + d);
            Ks[(d + 0) * KS_STRIDE + lr] = kv.x;
            Ks[(d + 1) * KS_STRIDE + lr] = kv.y;
            Ks[(d + 2) * KS_STRIDE + lr] = kv.z;
            Ks[(d + 3) * KS_STRIDE + lr] = kv.w;
            float4 vv = *(const float4*)(Vb + (size_t)(k0 + lr) * HD_ + d);
            *(float4*)(Vs + lr * VS_STRIDE + d) = vv;
        }
        __syncthreads();

        ull s2[4][4];
#pragma unroll
        for (int ip = 0; ip < 4; ++ip)
#pragma unroll
            for (int j = 0; j < 4; ++j) s2[ip][j] = 0ull;

#pragma unroll 4
        for (int d = 0; d < 64; ++d) {
            ull a2[4];
#pragma unroll
            for (int ip = 0; ip < 4; ++ip)
                a2[ip] = *(const ull*)(Qs + d * QS_STRIDE + r0 + 2 * ip);
            float4 b4 = *(const float4*)(Ks + d * KS_STRIDE + c0);
            ull rb2[4] = {dup2(b4.x), dup2(b4.y), dup2(b4.z), dup2(b4.w)};
#pragma unroll
            for (int ip = 0; ip < 4; ++ip)
#pragma unroll
                for (int j = 0; j < 4; ++j)
                    s2[ip][j] = fma2(a2[ip], rb2[j], s2[ip][j]);
        }

        float acc[8][4];
#pragma unroll
        for (int ip = 0; ip < 4; ++ip)
#pragma unroll
            for (int j = 0; j < 4; ++j)
                upk2(s2[ip][j], acc[2 * ip][j], acc[2 * ip + 1][j]);

#pragma unroll
        for (int i = 0; i < 8; ++i) {
            float mt = fmaxf(fmaxf(acc[i][0], acc[i][1]), fmaxf(acc[i][2], acc[i][3]));
#pragma unroll
            for (int off = 1; off < 16; off <<= 1)
                mt = fmaxf(mt, __shfl_xor_sync(0xffffffffu, mt, off));
            float mn = fmaxf(m[i], mt);
            float corr = __expf(m[i] - mn);
            m[i] = mn;
            l[i] *= corr;
            ull c2 = dup2(corr);
            O2[i][0] = mul2(O2[i][0], c2);
            O2[i][1] = mul2(O2[i][1], c2);

            float rs = 0.0f;
#pragma unroll
            for (int j = 0; j < 4; ++j) {
                float pv = __expf(acc[i][j] - mn);
                acc[i][j] = pv;
                rs += pv;
            }
#pragma unroll
            for (int off = 1; off < 16; off <<= 1)
                rs += __shfl_xor_sync(0xffffffffu, rs, off);
            l[i] += rs;
        }

#pragma unroll
        for (int i = 0; i < 8; ++i)
            *(float4*)(Ps + (r0 + i) * PS_STRIDE + c0) =
                make_float4(acc[i][0], acc[i][1], acc[i][2], acc[i][3]);
        __syncthreads();

#pragma unroll 2
        for (int kk4 = 0; kk4 < 16; ++kk4) {
            const int kk = kk4 * 4;
            ulonglong2 v0 = *(const ulonglong2*)(Vs + (kk + 0) * VS_STRIDE + c0);
            ulonglong2 v1 = *(const ulonglong2*)(Vs + (kk + 1) * VS_STRIDE + c0);
            ulonglong2 v2 = *(const ulonglong2*)(Vs + (kk + 2) * VS_STRIDE + c0);
            ulonglong2 v3 = *(const ulonglong2*)(Vs + (kk + 3) * VS_STRIDE + c0);
#pragma unroll
            for (int i = 0; i < 8; ++i) {
                float4 pv = *(const float4*)(Ps + (r0 + i) * PS_STRIDE + kk);
                ull p0 = dup2(pv.x), p1 = dup2(pv.y), p2 = dup2(pv.z), p3 = dup2(pv.w);
                O2[i][0] = fma2(p0, v0.x, O2[i][0]);
                O2[i][1] = fma2(p0, v0.y, O2[i][1]);
                O2[i][0] = fma2(p1, v1.x, O2[i][0]);
                O2[i][1] = fma2(p1, v1.y, O2[i][1]);
                O2[i][0] = fma2(p2, v2.x, O2[i][0]);
                O2[i][1] = fma2(p2, v2.y, O2[i][1]);
                O2[i][0] = fma2(p3, v3.x, O2[i][0]);
                O2[i][1] = fma2(p3, v3.y, O2[i][1]);
            }
        }
    }

#pragma unroll
    for (int i = 0; i < 8; ++i) {
        float rl = 1.0f / l[i];
        float o0, o1, o2, o3;
        upk2(O2[i][0], o0, o1);
        upk2(O2[i][1], o2, o3);
        float4 o = make_float4(o0 * rl, o1 * rl, o2 * rl, o3 * rl);
        *(float4*)(g_y + (size_t)(b * T_ + q0 + r0 + i) * C_ + h * HD_ + c0) = o;
    }
}

// ============================================================================
// launch
// ============================================================================
extern "C" void kernel_launch(void* const* d_in, const int* in_sizes, int n_in,
                              void* d_out, int out_size)
{
    const float* x      = (const float*)d_in[0];
    const float* w_attn = (const float*)d_in[1];
    const float* w_proj = (const float*)d_in[2];
    float* out = (float*)d_out;

    float* qkv_ptr; cudaGetSymbolAddress((void**)&qkv_ptr, g_qkv);
    float* y_ptr;   cudaGetSymbolAddress((void**)&y_ptr,   g_y);

    cudaFuncSetAttribute(flash_attn, cudaFuncAttributeMaxDynamicSharedMemorySize, FLASH_SMEM);
    cudaFuncSetAttribute(gemm_tc, cudaFuncAttributeMaxDynamicSharedMemorySize, GEMM_SMEM);

    // 1) QKV = x @ w_attn^T : (8192, 3072) via mma.sync tf32
    gemm_tc<<<dim3(QKV_N / 128, M_ROWS / 128), 256, GEMM_SMEM>>>(
        x, w_attn, qkv_ptr, M_ROWS, QKV_N, C_);

    // 2) RoPE + rearrange
    {
        int n = B_ * T_ * H_ * (HD_ / 2);
        rope_rearrange<<<(n + 255) / 256, 256>>>(qkv_ptr);
    }

    // 3) flash attention -> g_y (B,T,C)
    flash_attn<<<dim3(T_ / 128, B_ * H_), 256, FLASH_SMEM>>>();

    // 4) out = y @ w_proj^T : (8192, 1024) via mma.sync tf32
    gemm_tc<<<dim3(C_ / 128, M_ROWS / 128), 256, GEMM_SMEM>>>(
        y_ptr, w_proj, out, M_ROWS, C_, C_);
}

// round 7
// speedup vs baseline: 2.1774x; 1.5680x over previous
#include <cuda_runtime.h>
#include <cuda_bf16.h>
#include <math.h>
#include <cstdint>

// Problem constants (fixed shapes from reference)
#define B_  4
#define T_  2048
#define C_  1024
#define H_  16
#define HD_ 64
#define M_ROWS (B_ * T_)          // 8192
#define QKV_N  (3 * C_)           // 3072

// -------- scratch (device globals; no allocation allowed) --------
__device__ float g_qkv[(size_t)M_ROWS * QKV_N];        // 96 MB (B*T, 3C)
__device__ float g_q[(size_t)B_ * H_ * T_ * HD_];      // 32 MB (B*H, T, hd) roped+scaled
__device__ float g_k[(size_t)B_ * H_ * T_ * HD_];      // 32 MB
__device__ float g_v[(size_t)B_ * H_ * T_ * HD_];      // 32 MB
__device__ float g_y[(size_t)M_ROWS * C_];             // 32 MB (B, T, C) attention output

// ---- tf32 helpers ----
__device__ __forceinline__ uint32_t f2tf32(float x) {
    uint32_t r; asm("cvt.rna.tf32.f32 %0, %1;" : "=r"(r) : "f"(x)); return r;
}
// D = A(16x8, tf32 row) * B(8x8, tf32 col) + D, fp32 accum
__device__ __forceinline__ void mma16n8k8(float c[4], const uint32_t a[4], const uint32_t b[2]) {
    asm volatile(
        "mma.sync.aligned.m16n8k8.row.col.f32.tf32.tf32.f32 "
        "{%0,%1,%2,%3}, {%4,%5,%6,%7}, {%8,%9}, {%0,%1,%2,%3};"
        : "+f"(c[0]), "+f"(c[1]), "+f"(c[2]), "+f"(c[3])
        : "r"(a[0]), "r"(a[1]), "r"(a[2]), "r"(a[3]), "r"(b[0]), "r"(b[1]));
}

// ============================================================================
// Tensor-core TF32 GEMM (NT) — unchanged from Round 6 passing version.
// ============================================================================
#define GEMM_SMEM (16384 * 4)    // 2 bufs x (A 4096 + B 4096) uint32 = 64KB

__global__ void __launch_bounds__(256) gemm_tc(
    const float* __restrict__ A, const float* __restrict__ Bm,
    float* __restrict__ C, int M, int N, int K)
{
    extern __shared__ uint32_t sm[];

    const int tid  = threadIdx.x;
    const int lane = tid & 31;
    const int wid  = tid >> 5;
    const int wm = wid & 1;
    const int wn = wid >> 1;
    const int g = lane >> 2;
    const int t = lane & 3;
    const int bm = blockIdx.y * 128;
    const int bn = blockIdx.x * 128;

    const int lrow = tid >> 3;
    const int lu   = tid & 7;

    float acc[4][4][4];
#pragma unroll
    for (int mt = 0; mt < 4; ++mt)
#pragma unroll
        for (int nt = 0; nt < 4; ++nt)
#pragma unroll
            for (int q = 0; q < 4; ++q) acc[mt][nt][q] = 0.0f;

    float4 ra[4], rb[4];

    auto ldg_stage = [&](int k0) {
#pragma unroll
        for (int p = 0; p < 4; ++p) {
            int row = lrow + p * 32;
            ra[p] = *(const float4*)(A  + (size_t)(bm + row) * K + k0 + lu * 4);
            rb[p] = *(const float4*)(Bm + (size_t)(bn + row) * K + k0 + lu * 4);
        }
    };
    auto sts_stage = [&](int buf) {
#pragma unroll
        for (int p = 0; p < 4; ++p) {
            int row = lrow + p * 32;
            int u = lu ^ (row & 7);
            uint4 ta = make_uint4(f2tf32(ra[p].x), f2tf32(ra[p].y), f2tf32(ra[p].z), f2tf32(ra[p].w));
            uint4 tb = make_uint4(f2tf32(rb[p].x), f2tf32(rb[p].y), f2tf32(rb[p].z), f2tf32(rb[p].w));
            *(uint4*)(sm + buf * 4096 + row * 32 + u * 4) = ta;
            *(uint4*)(sm + 8192 + buf * 4096 + row * 32 + u * 4) = tb;
        }
    };

    ldg_stage(0);
    sts_stage(0);
    __syncthreads();

    const int nk = K >> 5;
    for (int kt = 0; kt < nk; ++kt) {
        const int buf = kt & 1;
        if (kt + 1 < nk) ldg_stage((kt + 1) << 5);

        const uint32_t* Asb = sm + buf * 4096;
        const uint32_t* Bsb = sm + 8192 + buf * 4096;

#pragma unroll
        for (int c8 = 0; c8 < 4; ++c8) {
            const int u0 = (2 * c8) ^ g;
            const int u1 = u0 ^ 1;

            uint32_t af[4][4];
#pragma unroll
            for (int mt = 0; mt < 4; ++mt) {
                const int r0 = wm * 64 + mt * 16 + g;
                af[mt][0] = Asb[r0 * 32 + u0 * 4 + t];
                af[mt][1] = Asb[(r0 + 8) * 32 + u0 * 4 + t];
                af[mt][2] = Asb[r0 * 32 + u1 * 4 + t];
                af[mt][3] = Asb[(r0 + 8) * 32 + u1 * 4 + t];
            }
            uint32_t bf[4][2];
#pragma unroll
            for (int nt = 0; nt < 4; ++nt) {
                const int n0 = wn * 32 + nt * 8 + g;
                bf[nt][0] = Bsb[n0 * 32 + u0 * 4 + t];
                bf[nt][1] = Bsb[n0 * 32 + u1 * 4 + t];
            }
#pragma unroll
            for (int mt = 0; mt < 4; ++mt)
#pragma unroll
                for (int nt = 0; nt < 4; ++nt)
                    mma16n8k8(acc[mt][nt], af[mt], bf[nt]);
        }

        if (kt + 1 < nk) sts_stage(buf ^ 1);
        __syncthreads();
    }

#pragma unroll
    for (int mt = 0; mt < 4; ++mt) {
        const int row = bm + wm * 64 + mt * 16 + g;
#pragma unroll
        for (int nt = 0; nt < 4; ++nt) {
            const int col = bn + wn * 32 + nt * 8 + 2 * t;
            *(float2*)(C + (size_t)row * N + col)       = make_float2(acc[mt][nt][0], acc[mt][nt][1]);
            *(float2*)(C + (size_t)(row + 8) * N + col) = make_float2(acc[mt][nt][2], acc[mt][nt][3]);
        }
    }
}

// ============================================================================
// RoPE + rearrange: qkv (B*T, 3C) -> Q/K/V (B*H, T, hd)
// ============================================================================
__global__ __launch_bounds__(256) void rope_rearrange(const float* __restrict__ qkv)
{
    int idx = blockIdx.x * blockDim.x + threadIdx.x;
    if (idx >= B_ * T_ * H_ * (HD_ / 2)) return;

    int i = idx & 31;               // pair index 0..31
    int h = (idx >> 5) & 15;
    int t = (idx >> 9) & 2047;
    int b = idx >> 20;

    const float* src = qkv + (size_t)(b * T_ + t) * QKV_N + h * HD_ + 2 * i;

    double inv = exp2(-(double)i * (13.287712379549449595 / 32.0)); // 10000^(-i/32)
    double ang = (double)t * inv;
    double ds, dc;
    sincos(ang, &ds, &dc);
    float s = (float)ds, c = (float)dc;

    float q0 = src[0],       q1 = src[1];
    float k0 = src[C_],      k1 = src[C_ + 1];
    float2 v2 = *(const float2*)(src + 2 * C_);

    size_t dst = ((size_t)(b * H_ + h) * T_ + t) * HD_ + 2 * i;
    const float qs = 0.125f;  // 1/sqrt(64)
    g_q[dst]     = (q0 * c - q1 * s) * qs;
    g_q[dst + 1] = (q0 * s + q1 * c) * qs;
    g_k[dst]     = k0 * c - k1 * s;
    g_k[dst + 1] = k0 * s + k1 * c;
    *(float2*)(g_v + dst) = v2;
}

// ============================================================================
// Tensor-core flash attention: Bq=128, Bk=64, hd=64. 256 threads (8 warps),
// warp = 16 q-rows (M-split only -> softmax row reductions stay in-quad).
// smem (tf32 bits, stride 68):
//   Qs [128][68]  q-row major
//   Ks [64][68]   key-major     (QK B-operand)
//   Vs [64][68]   d-major (transposed at load; PV B-operand)
//   Pw [8][16][68] per-warp P staging (C-frag -> A-frag re-gather)
// ============================================================================
#define FA_STR 68
#define FA_QS  0
#define FA_KS  (128 * FA_STR)                 // 8704
#define FA_VS  (FA_KS + 64 * FA_STR)          // 13056
#define FA_PW  (FA_VS + 64 * FA_STR)          // 17408
#define FLASH_SMEM ((FA_PW + 8 * 16 * FA_STR) * 4)   // 104448 bytes

__global__ void __launch_bounds__(256) flash_tc()
{
    extern __shared__ uint32_t fsm[];
    uint32_t* Qs = fsm + FA_QS;
    uint32_t* Ks = fsm + FA_KS;
    uint32_t* Vs = fsm + FA_VS;
    uint32_t* Pw = fsm + FA_PW;

    const int bh = blockIdx.y;                // 0..63
    const int b  = bh >> 4;
    const int h  = bh & 15;
    const int q0 = blockIdx.x * 128;

    const float* Qb = g_q + (size_t)bh * T_ * HD_;
    const float* Kb = g_k + (size_t)bh * T_ * HD_;
    const float* Vb = g_v + (size_t)bh * T_ * HD_;

    const int tid  = threadIdx.x;
    const int lane = tid & 31;
    const int wid  = tid >> 5;
    const int g = lane >> 2;       // quad row
    const int t = lane & 3;        // quad col
    const int qr = wid * 16;       // warp's q-row base within tile
    uint32_t* Pme = Pw + wid * (16 * FA_STR);

    // ---- load Q tile (once), tf32, natural row-major ----
    {
        const int row = tid >> 1;
        const int d0  = (tid & 1) * 32;
#pragma unroll
        for (int p = 0; p < 8; ++p) {
            float4 v = *(const float4*)(Qb + (size_t)(q0 + row) * HD_ + d0 + p * 4);
            *(uint4*)(Qs + row * FA_STR + d0 + p * 4) =
                make_uint4(f2tf32(v.x), f2tf32(v.y), f2tf32(v.z), f2tf32(v.w));
        }
    }

    // K/V register staging: key = tid>>2 (0..63), d-chunk = (tid&3)*16
    const int lkey = tid >> 2;
    const int ld0  = (tid & 3) * 16;
    float4 kreg[4], vreg[4];
    auto ldg_kv = [&](int k0) {
#pragma unroll
        for (int p = 0; p < 4; ++p) {
            kreg[p] = *(const float4*)(Kb + (size_t)(k0 + lkey) * HD_ + ld0 + p * 4);
            vreg[p] = *(const float4*)(Vb + (size_t)(k0 + lkey) * HD_ + ld0 + p * 4);
        }
    };

    // online softmax state (rows qr+g and qr+g+8), O fragments
    float m0 = -3.0e38f, m1 = -3.0e38f, l0 = 0.0f, l1 = 0.0f;
    float oacc[8][4];
#pragma unroll
    for (int nt = 0; nt < 8; ++nt)
#pragma unroll
        for (int q = 0; q < 4; ++q) oacc[nt][q] = 0.0f;

    ldg_kv(0);

    for (int kt = 0; kt < T_ / 64; ++kt) {
        __syncthreads();             // previous tile's Ks/Vs readers done
        // commit staged K (key-major) and V (transposed to d-major)
#pragma unroll
        for (int p = 0; p < 4; ++p) {
            const int d = ld0 + p * 4;
            *(uint4*)(Ks + lkey * FA_STR + d) =
                make_uint4(f2tf32(kreg[p].x), f2tf32(kreg[p].y), f2tf32(kreg[p].z), f2tf32(kreg[p].w));
            Vs[(d + 0) * FA_STR + lkey] = f2tf32(vreg[p].x);
            Vs[(d + 1) * FA_STR + lkey] = f2tf32(vreg[p].y);
            Vs[(d + 2) * FA_STR + lkey] = f2tf32(vreg[p].z);
            Vs[(d + 3) * FA_STR + lkey] = f2tf32(vreg[p].w);
        }
        __syncthreads();
        if (kt + 1 < T_ / 64) ldg_kv((kt + 1) * 64);

        // ---- S = Q K^T : warp computes 16x64 ----
        float sacc[8][4];
#pragma unroll
        for (int nt = 0; nt < 8; ++nt)
#pragma unroll
            for (int q = 0; q < 4; ++q) sacc[nt][q] = 0.0f;

#pragma unroll
        for (int c8 = 0; c8 < 8; ++c8) {
            uint32_t a[4];
            a[0] = Qs[(qr + g) * FA_STR + c8 * 8 + t];
            a[1] = Qs[(qr + g + 8) * FA_STR + c8 * 8 + t];
            a[2] = Qs[(qr + g) * FA_STR + c8 * 8 + t + 4];
            a[3] = Qs[(qr + g + 8) * FA_STR + c8 * 8 + t + 4];
#pragma unroll
            for (int nt = 0; nt < 8; ++nt) {
                uint32_t bb[2];
                bb[0] = Ks[(nt * 8 + g) * FA_STR + c8 * 8 + t];
                bb[1] = Ks[(nt * 8 + g) * FA_STR + c8 * 8 + t + 4];
                mma16n8k8(sacc[nt], a, bb);
            }
        }

        // ---- online softmax (rows g and g+8; reduce over quad lanes t) ----
        float tm0 = -3.0e38f, tm1 = -3.0e38f;
#pragma unroll
        for (int nt = 0; nt < 8; ++nt) {
            tm0 = fmaxf(tm0, fmaxf(sacc[nt][0], sacc[nt][1]));
            tm1 = fmaxf(tm1, fmaxf(sacc[nt][2], sacc[nt][3]));
        }
#pragma unroll
        for (int off = 1; off < 4; off <<= 1) {
            tm0 = fmaxf(tm0, __shfl_xor_sync(0xffffffffu, tm0, off));
            tm1 = fmaxf(tm1, __shfl_xor_sync(0xffffffffu, tm1, off));
        }
        const float mn0 = fmaxf(m0, tm0);
        const float mn1 = fmaxf(m1, tm1);
        const float corr0 = __expf(m0 - mn0);
        const float corr1 = __expf(m1 - mn1);
        m0 = mn0; m1 = mn1;

        float rs0 = 0.0f, rs1 = 0.0f;
#pragma unroll
        for (int nt = 0; nt < 8; ++nt) {
            float p0 = __expf(sacc[nt][0] - mn0);
            float p1 = __expf(sacc[nt][1] - mn0);
            float p2 = __expf(sacc[nt][2] - mn1);
            float p3 = __expf(sacc[nt][3] - mn1);
            rs0 += p0 + p1;
            rs1 += p2 + p3;
            Pme[g * FA_STR + nt * 8 + 2 * t]           = f2tf32(p0);
            Pme[g * FA_STR + nt * 8 + 2 * t + 1]       = f2tf32(p1);
            Pme[(g + 8) * FA_STR + nt * 8 + 2 * t]     = f2tf32(p2);
            Pme[(g + 8) * FA_STR + nt * 8 + 2 * t + 1] = f2tf32(p3);
#pragma unroll
            for (int q = 0; q < 2; ++q) { oacc[nt][q] *= corr0; oacc[nt][q + 2] *= corr1; }
        }
#pragma unroll
        for (int off = 1; off < 4; off <<= 1) {
            rs0 += __shfl_xor_sync(0xffffffffu, rs0, off);
            rs1 += __shfl_xor_sync(0xffffffffu, rs1, off);
        }
        l0 = l0 * corr0 + rs0;
        l1 = l1 * corr1 + rs1;

        __syncwarp();

        // ---- O += P V : warp computes 16x64 over 64 keys ----
#pragma unroll
        for (int kk = 0; kk < 8; ++kk) {
            uint32_t a[4];
            a[0] = Pme[g * FA_STR + kk * 8 + t];
            a[1] = Pme[(g + 8) * FA_STR + kk * 8 + t];
            a[2] = Pme[g * FA_STR + kk * 8 + t + 4];
            a[3] = Pme[(g + 8) * FA_STR + kk * 8 + t + 4];
#pragma unroll
            for (int nt = 0; nt < 8; ++nt) {
                uint32_t bb[2];
                bb[0] = Vs[(nt * 8 + g) * FA_STR + kk * 8 + t];
                bb[1] = Vs[(nt * 8 + g) * FA_STR + kk * 8 + t + 4];
                mma16n8k8(oacc[nt], a, bb);
            }
        }
        __syncwarp();   // Pme reads done before next tile's stores
    }

    // ---- epilogue: normalize, write (B, T, C) ----
    const float rl0 = 1.0f / l0;
    const float rl1 = 1.0f / l1;
    const size_t row0 = (size_t)(b * T_ + q0 + qr + g);
    const size_t row1 = row0 + 8;
#pragma unroll
    for (int nt = 0; nt < 8; ++nt) {
        const int col = h * HD_ + nt * 8 + 2 * t;
        *(float2*)(g_y + row0 * C_ + col) = make_float2(oacc[nt][0] * rl0, oacc[nt][1] * rl0);
        *(float2*)(g_y + row1 * C_ + col) = make_float2(oacc[nt][2] * rl1, oacc[nt][3] * rl1);
    }
}

// ============================================================================
// launch
// ============================================================================
extern "C" void kernel_launch(void* const* d_in, const int* in_sizes, int n_in,
                              void* d_out, int out_size)
{
    const float* x      = (const float*)d_in[0];
    const float* w_attn = (const float*)d_in[1];
    const float* w_proj = (const float*)d_in[2];
    float* out = (float*)d_out;

    float* qkv_ptr; cudaGetSymbolAddress((void**)&qkv_ptr, g_qkv);
    float* y_ptr;   cudaGetSymbolAddress((void**)&y_ptr,   g_y);

    cudaFuncSetAttribute(flash_tc, cudaFuncAttributeMaxDynamicSharedMemorySize, FLASH_SMEM);
    cudaFuncSetAttribute(gemm_tc, cudaFuncAttributeMaxDynamicSharedMemorySize, GEMM_SMEM);

    // 1) QKV = x @ w_attn^T : (8192, 3072) via mma.sync tf32
    gemm_tc<<<dim3(QKV_N / 128, M_ROWS / 128), 256, GEMM_SMEM>>>(
        x, w_attn, qkv_ptr, M_ROWS, QKV_N, C_);

    // 2) RoPE + rearrange
    {
        int n = B_ * T_ * H_ * (HD_ / 2);
        rope_rearrange<<<(n + 255) / 256, 256>>>(qkv_ptr);
    }

    // 3) flash attention -> g_y (B,T,C) via mma.sync tf32
    flash_tc<<<dim3(T_ / 128, B_ * H_), 256, FLASH_SMEM>>>();

    // 4) out = y @ w_proj^T : (8192, 1024) via mma.sync tf32
    gemm_tc<<<dim3(C_ / 128, M_ROWS / 128), 256, GEMM_SMEM>>>(
        y_ptr, w_proj, out, M_ROWS, C_, C_);
}

// round 8
// speedup vs baseline: 2.2631x; 1.0394x over previous
#include <cuda_runtime.h>
#include <cuda_bf16.h>
#include <math.h>
#include <cstdint>

// Problem constants (fixed shapes from reference)
#define B_  4
#define T_  2048
#define C_  1024
#define H_  16
#define HD_ 64
#define M_ROWS (B_ * T_)          // 8192
#define QKV_N  (3 * C_)           // 3072

// -------- scratch (device globals; no allocation allowed) --------
__device__ float g_qkv[(size_t)M_ROWS * QKV_N];        // 96 MB (B*T, 3C)
__device__ float g_q[(size_t)B_ * H_ * T_ * HD_];      // 32 MB (B*H, T, hd) roped+scaled
__device__ float g_k[(size_t)B_ * H_ * T_ * HD_];      // 32 MB
__device__ float g_v[(size_t)B_ * H_ * T_ * HD_];      // 32 MB
__device__ float g_y[(size_t)M_ROWS * C_];             // 32 MB (B, T, C) attention output

// ---- tf32 helpers ----
__device__ __forceinline__ uint32_t f2tf32(float x) {
    uint32_t r; asm("cvt.rna.tf32.f32 %0, %1;" : "=r"(r) : "f"(x)); return r;
}
// D = A(16x8, tf32 row) * B(8x8, tf32 col) + D, fp32 accum
__device__ __forceinline__ void mma16n8k8(float c[4], const uint32_t a[4], const uint32_t b[2]) {
    asm volatile(
        "mma.sync.aligned.m16n8k8.row.col.f32.tf32.tf32.f32 "
        "{%0,%1,%2,%3}, {%4,%5,%6,%7}, {%8,%9}, {%0,%1,%2,%3};"
        : "+f"(c[0]), "+f"(c[1]), "+f"(c[2]), "+f"(c[3])
        : "r"(a[0]), "r"(a[1]), "r"(a[2]), "r"(a[3]), "r"(b[0]), "r"(b[1]));
}

// ============================================================================
// Tensor-core TF32 GEMM (NT) — unchanged from Round 6/7 passing version.
// ============================================================================
#define GEMM_SMEM (16384 * 4)    // 2 bufs x (A 4096 + B 4096) uint32 = 64KB

__global__ void __launch_bounds__(256) gemm_tc(
    const float* __restrict__ A, const float* __restrict__ Bm,
    float* __restrict__ C, int M, int N, int K)
{
    extern __shared__ uint32_t sm[];

    const int tid  = threadIdx.x;
    const int lane = tid & 31;
    const int wid  = tid >> 5;
    const int wm = wid & 1;
    const int wn = wid >> 1;
    const int g = lane >> 2;
    const int t = lane & 3;
    const int bm = blockIdx.y * 128;
    const int bn = blockIdx.x * 128;

    const int lrow = tid >> 3;
    const int lu   = tid & 7;

    float acc[4][4][4];
#pragma unroll
    for (int mt = 0; mt < 4; ++mt)
#pragma unroll
        for (int nt = 0; nt < 4; ++nt)
#pragma unroll
            for (int q = 0; q < 4; ++q) acc[mt][nt][q] = 0.0f;

    float4 ra[4], rb[4];

    auto ldg_stage = [&](int k0) {
#pragma unroll
        for (int p = 0; p < 4; ++p) {
            int row = lrow + p * 32;
            ra[p] = *(const float4*)(A  + (size_t)(bm + row) * K + k0 + lu * 4);
            rb[p] = *(const float4*)(Bm + (size_t)(bn + row) * K + k0 + lu * 4);
        }
    };
    auto sts_stage = [&](int buf) {
#pragma unroll
        for (int p = 0; p < 4; ++p) {
            int row = lrow + p * 32;
            int u = lu ^ (row & 7);
            uint4 ta = make_uint4(f2tf32(ra[p].x), f2tf32(ra[p].y), f2tf32(ra[p].z), f2tf32(ra[p].w));
            uint4 tb = make_uint4(f2tf32(rb[p].x), f2tf32(rb[p].y), f2tf32(rb[p].z), f2tf32(rb[p].w));
            *(uint4*)(sm + buf * 4096 + row * 32 + u * 4) = ta;
            *(uint4*)(sm + 8192 + buf * 4096 + row * 32 + u * 4) = tb;
        }
    };

    ldg_stage(0);
    sts_stage(0);
    __syncthreads();

    const int nk = K >> 5;
    for (int kt = 0; kt < nk; ++kt) {
        const int buf = kt & 1;
        if (kt + 1 < nk) ldg_stage((kt + 1) << 5);

        const uint32_t* Asb = sm + buf * 4096;
        const uint32_t* Bsb = sm + 8192 + buf * 4096;

#pragma unroll
        for (int c8 = 0; c8 < 4; ++c8) {
            const int u0 = (2 * c8) ^ g;
            const int u1 = u0 ^ 1;

            uint32_t af[4][4];
#pragma unroll
            for (int mt = 0; mt < 4; ++mt) {
                const int r0 = wm * 64 + mt * 16 + g;
                af[mt][0] = Asb[r0 * 32 + u0 * 4 + t];
                af[mt][1] = Asb[(r0 + 8) * 32 + u0 * 4 + t];
                af[mt][2] = Asb[r0 * 32 + u1 * 4 + t];
                af[mt][3] = Asb[(r0 + 8) * 32 + u1 * 4 + t];
            }
            uint32_t bf[4][2];
#pragma unroll
            for (int nt = 0; nt < 4; ++nt) {
                const int n0 = wn * 32 + nt * 8 + g;
                bf[nt][0] = Bsb[n0 * 32 + u0 * 4 + t];
                bf[nt][1] = Bsb[n0 * 32 + u1 * 4 + t];
            }
#pragma unroll
            for (int mt = 0; mt < 4; ++mt)
#pragma unroll
                for (int nt = 0; nt < 4; ++nt)
                    mma16n8k8(acc[mt][nt], af[mt], bf[nt]);
        }

        if (kt + 1 < nk) sts_stage(buf ^ 1);
        __syncthreads();
    }

#pragma unroll
    for (int mt = 0; mt < 4; ++mt) {
        const int row = bm + wm * 64 + mt * 16 + g;
#pragma unroll
        for (int nt = 0; nt < 4; ++nt) {
            const int col = bn + wn * 32 + nt * 8 + 2 * t;
            *(float2*)(C + (size_t)row * N + col)       = make_float2(acc[mt][nt][0], acc[mt][nt][1]);
            *(float2*)(C + (size_t)(row + 8) * N + col) = make_float2(acc[mt][nt][2], acc[mt][nt][3]);
        }
    }
}

// ============================================================================
// RoPE + rearrange: qkv (B*T, 3C) -> Q/K/V (B*H, T, hd)
// ============================================================================
__global__ __launch_bounds__(256) void rope_rearrange(const float* __restrict__ qkv)
{
    int idx = blockIdx.x * blockDim.x + threadIdx.x;
    if (idx >= B_ * T_ * H_ * (HD_ / 2)) return;

    int i = idx & 31;               // pair index 0..31
    int h = (idx >> 5) & 15;
    int t = (idx >> 9) & 2047;
    int b = idx >> 20;

    const float* src = qkv + (size_t)(b * T_ + t) * QKV_N + h * HD_ + 2 * i;

    double inv = exp2(-(double)i * (13.287712379549449595 / 32.0)); // 10000^(-i/32)
    double ang = (double)t * inv;
    double ds, dc;
    sincos(ang, &ds, &dc);
    float s = (float)ds, c = (float)dc;

    float q0 = src[0],       q1 = src[1];
    float k0 = src[C_],      k1 = src[C_ + 1];
    float2 v2 = *(const float2*)(src + 2 * C_);

    size_t dst = ((size_t)(b * H_ + h) * T_ + t) * HD_ + 2 * i;
    const float qs = 0.125f;  // 1/sqrt(64)
    g_q[dst]     = (q0 * c - q1 * s) * qs;
    g_q[dst + 1] = (q0 * s + q1 * c) * qs;
    g_k[dst]     = k0 * c - k1 * s;
    g_k[dst + 1] = k0 * s + k1 * c;
    *(float2*)(g_v + dst) = v2;
}

// ============================================================================
// Tensor-core flash attention v3: Bq=128, Bk=64, hd=64. 256 threads (8 warps),
// warp = 16 q-rows. Q fragments in REGISTERS (loop-invariant). K and V both
// key-major in smem (no transpose): K stride 68 (B-frag banks 4g+t, conflict-
// free), V stride 72 (B-frag banks 8t+g, conflict-free). Per-warp P staging
// stride 68. smem ~69KB -> 2 CTAs/SM for latency hiding.
// ============================================================================
#define FA_KSTR 68
#define FA_VSTR 72
#define FA_PSTR 68
#define FA_KS  0
#define FA_VS  (64 * FA_KSTR)                     // 4352
#define FA_PW  (FA_VS + 64 * FA_VSTR)             // 8960
#define FLASH_SMEM ((FA_PW + 8 * 16 * FA_PSTR) * 4)   // 70656 bytes

__global__ void __launch_bounds__(256, 2) flash_tc()
{
    extern __shared__ uint32_t fsm[];
    uint32_t* Ks = fsm + FA_KS;
    uint32_t* Vs = fsm + FA_VS;
    uint32_t* Pw = fsm + FA_PW;

    const int bh = blockIdx.y;                // 0..63
    const int b  = bh >> 4;
    const int h  = bh & 15;
    const int q0 = blockIdx.x * 128;

    const float* Qb = g_q + (size_t)bh * T_ * HD_;
    const float* Kb = g_k + (size_t)bh * T_ * HD_;
    const float* Vb = g_v + (size_t)bh * T_ * HD_;

    const int tid  = threadIdx.x;
    const int lane = tid & 31;
    const int wid  = tid >> 5;
    const int g = lane >> 2;       // quad row
    const int t = lane & 3;        // quad col
    const int qr = wid * 16;       // warp's q-row base within tile
    uint32_t* Pme = Pw + wid * (16 * FA_PSTR);

    // ---- Q fragments in registers (loop-invariant) ----
    uint32_t qf[8][4];
    {
        const float* qrow0 = Qb + (size_t)(q0 + qr + g) * HD_;
        const float* qrow1 = qrow0 + 8 * HD_;
#pragma unroll
        for (int c8 = 0; c8 < 8; ++c8) {
            qf[c8][0] = f2tf32(qrow0[c8 * 8 + t]);
            qf[c8][1] = f2tf32(qrow1[c8 * 8 + t]);
            qf[c8][2] = f2tf32(qrow0[c8 * 8 + t + 4]);
            qf[c8][3] = f2tf32(qrow1[c8 * 8 + t + 4]);
        }
    }

    // K/V loader mapping: key = tid>>2 (0..63), d-chunk = (tid&3)*16
    const int lkey = tid >> 2;
    const int ld0  = (tid & 3) * 16;

    // online softmax state (rows qr+g and qr+g+8), O fragments
    float m0 = -3.0e38f, m1 = -3.0e38f, l0 = 0.0f, l1 = 0.0f;
    float oacc[8][4];
#pragma unroll
    for (int nt = 0; nt < 8; ++nt)
#pragma unroll
        for (int q = 0; q < 4; ++q) oacc[nt][q] = 0.0f;

    for (int kt = 0; kt < T_ / 64; ++kt) {
        const int k0 = kt * 64;
        __syncthreads();             // previous tile's Ks/Vs readers done
        // load K/V tile: LDG -> tf32 -> STS (single-buffered; co-resident CTA hides latency)
#pragma unroll
        for (int p = 0; p < 4; ++p) {
            const int d = ld0 + p * 4;
            float4 kv = *(const float4*)(Kb + (size_t)(k0 + lkey) * HD_ + d);
            float4 vv = *(const float4*)(Vb + (size_t)(k0 + lkey) * HD_ + d);
            *(uint4*)(Ks + lkey * FA_KSTR + d) =
                make_uint4(f2tf32(kv.x), f2tf32(kv.y), f2tf32(kv.z), f2tf32(kv.w));
            *(uint4*)(Vs + lkey * FA_VSTR + d) =
                make_uint4(f2tf32(vv.x), f2tf32(vv.y), f2tf32(vv.z), f2tf32(vv.w));
        }
        __syncthreads();

        // ---- S = Q K^T : warp computes 16x64 ----
        float sacc[8][4];
#pragma unroll
        for (int nt = 0; nt < 8; ++nt)
#pragma unroll
            for (int q = 0; q < 4; ++q) sacc[nt][q] = 0.0f;

#pragma unroll
        for (int c8 = 0; c8 < 8; ++c8) {
#pragma unroll
            for (int nt = 0; nt < 8; ++nt) {
                uint32_t bb[2];
                bb[0] = Ks[(nt * 8 + g) * FA_KSTR + c8 * 8 + t];
                bb[1] = Ks[(nt * 8 + g) * FA_KSTR + c8 * 8 + t + 4];
                mma16n8k8(sacc[nt], qf[c8], bb);
            }
        }

        // ---- online softmax (rows g and g+8; reduce over quad lanes t) ----
        float tm0 = -3.0e38f, tm1 = -3.0e38f;
#pragma unroll
        for (int nt = 0; nt < 8; ++nt) {
            tm0 = fmaxf(tm0, fmaxf(sacc[nt][0], sacc[nt][1]));
            tm1 = fmaxf(tm1, fmaxf(sacc[nt][2], sacc[nt][3]));
        }
#pragma unroll
        for (int off = 1; off < 4; off <<= 1) {
            tm0 = fmaxf(tm0, __shfl_xor_sync(0xffffffffu, tm0, off));
            tm1 = fmaxf(tm1, __shfl_xor_sync(0xffffffffu, tm1, off));
        }
        const float mn0 = fmaxf(m0, tm0);
        const float mn1 = fmaxf(m1, tm1);
        const float corr0 = __expf(m0 - mn0);
        const float corr1 = __expf(m1 - mn1);
        m0 = mn0; m1 = mn1;

        float rs0 = 0.0f, rs1 = 0.0f;
#pragma unroll
        for (int nt = 0; nt < 8; ++nt) {
            float p0 = __expf(sacc[nt][0] - mn0);
            float p1 = __expf(sacc[nt][1] - mn0);
            float p2 = __expf(sacc[nt][2] - mn1);
            float p3 = __expf(sacc[nt][3] - mn1);
            rs0 += p0 + p1;
            rs1 += p2 + p3;
            Pme[g * FA_PSTR + nt * 8 + 2 * t]           = f2tf32(p0);
            Pme[g * FA_PSTR + nt * 8 + 2 * t + 1]       = f2tf32(p1);
            Pme[(g + 8) * FA_PSTR + nt * 8 + 2 * t]     = f2tf32(p2);
            Pme[(g + 8) * FA_PSTR + nt * 8 + 2 * t + 1] = f2tf32(p3);
#pragma unroll
            for (int q = 0; q < 2; ++q) { oacc[nt][q] *= corr0; oacc[nt][q + 2] *= corr1; }
        }
#pragma unroll
        for (int off = 1; off < 4; off <<= 1) {
            rs0 += __shfl_xor_sync(0xffffffffu, rs0, off);
            rs1 += __shfl_xor_sync(0xffffffffu, rs1, off);
        }
        l0 = l0 * corr0 + rs0;
        l1 = l1 * corr1 + rs1;

        __syncwarp();

        // ---- O += P V : warp computes 16x64 over 64 keys ----
#pragma unroll
        for (int kk = 0; kk < 8; ++kk) {
            uint32_t a[4];
            a[0] = Pme[g * FA_PSTR + kk * 8 + t];
            a[1] = Pme[(g + 8) * FA_PSTR + kk * 8 + t];
            a[2] = Pme[g * FA_PSTR + kk * 8 + t + 4];
            a[3] = Pme[(g + 8) * FA_PSTR + kk * 8 + t + 4];
#pragma unroll
            for (int nt = 0; nt < 8; ++nt) {
                uint32_t bb[2];
                bb[0] = Vs[(kk * 8 + t) * FA_VSTR + nt * 8 + g];
                bb[1] = Vs[(kk * 8 + t + 4) * FA_VSTR + nt * 8 + g];
                mma16n8k8(oacc[nt], a, bb);
            }
        }
        __syncwarp();
    }

    // ---- epilogue: normalize, write (B, T, C) ----
    const float rl0 = 1.0f / l0;
    const float rl1 = 1.0f / l1;
    const size_t row0 = (size_t)(b * T_ + q0 + qr + g);
    const size_t row1 = row0 + 8;
#pragma unroll
    for (int nt = 0; nt < 8; ++nt) {
        const int col = h * HD_ + nt * 8 + 2 * t;
        *(float2*)(g_y + row0 * C_ + col) = make_float2(oacc[nt][0] * rl0, oacc[nt][1] * rl0);
        *(float2*)(g_y + row1 * C_ + col) = make_float2(oacc[nt][2] * rl1, oacc[nt][3] * rl1);
    }
}

// ============================================================================
// launch
// ============================================================================
extern "C" void kernel_launch(void* const* d_in, const int* in_sizes, int n_in,
                              void* d_out, int out_size)
{
    const float* x      = (const float*)d_in[0];
    const float* w_attn = (const float*)d_in[1];
    const float* w_proj = (const float*)d_in[2];
    float* out = (float*)d_out;

    float* qkv_ptr; cudaGetSymbolAddress((void**)&qkv_ptr, g_qkv);
    float* y_ptr;   cudaGetSymbolAddress((void**)&y_ptr,   g_y);

    cudaFuncSetAttribute(flash_tc, cudaFuncAttributeMaxDynamicSharedMemorySize, FLASH_SMEM);
    cudaFuncSetAttribute(gemm_tc, cudaFuncAttributeMaxDynamicSharedMemorySize, GEMM_SMEM);

    // 1) QKV = x @ w_attn^T : (8192, 3072) via mma.sync tf32
    gemm_tc<<<dim3(QKV_N / 128, M_ROWS / 128), 256, GEMM_SMEM>>>(
        x, w_attn, qkv_ptr, M_ROWS, QKV_N, C_);

    // 2) RoPE + rearrange
    {
        int n = B_ * T_ * H_ * (HD_ / 2);
        rope_rearrange<<<(n + 255) / 256, 256>>>(qkv_ptr);
    }

    // 3) flash attention -> g_y (B,T,C) via mma.sync tf32
    flash_tc<<<dim3(T_ / 128, B_ * H_), 256, FLASH_SMEM>>>();

    // 4) out = y @ w_proj^T : (8192, 1024) via mma.sync tf32
    gemm_tc<<<dim3(C_ / 128, M_ROWS / 128), 256, GEMM_SMEM>>>(
        y_ptr, w_proj, out, M_ROWS, C_, C_);
}

// round 9
// speedup vs baseline: 2.6049x; 1.1510x over previous
#include <cuda_runtime.h>
#include <cuda_bf16.h>
#include <math.h>
#include <cstdint>

// Problem constants (fixed shapes from reference)
#define B_  4
#define T_  2048
#define C_  1024
#define H_  16
#define HD_ 64
#define M_ROWS (B_ * T_)          // 8192
#define QKV_N  (3 * C_)           // 3072

// -------- scratch (device globals; no allocation allowed) --------
__device__ float    g_qkv[(size_t)M_ROWS * QKV_N];     // 96 MB (B*T, 3C) fp32
__device__ uint32_t g_q[(size_t)B_ * H_ * T_ * HD_];   // tf32 bits, roped+scaled
__device__ uint32_t g_k[(size_t)B_ * H_ * T_ * HD_];   // tf32 bits
__device__ uint32_t g_v[(size_t)B_ * H_ * T_ * HD_];   // tf32 bits
__device__ uint32_t g_y[(size_t)M_ROWS * C_];          // tf32 bits (B, T, C)
__device__ uint32_t g_xt[(size_t)M_ROWS * C_];         // tf32(x)
__device__ uint32_t g_wat[(size_t)QKV_N * C_];         // tf32(w_attn)
__device__ uint32_t g_wpt[(size_t)C_ * C_];            // tf32(w_proj)

// ---- tf32 / mma / cp.async helpers ----
__device__ __forceinline__ uint32_t f2tf32(float x) {
    uint32_t r; asm("cvt.rna.tf32.f32 %0, %1;" : "=r"(r) : "f"(x)); return r;
}
__device__ __forceinline__ void mma16n8k8(float c[4], const uint32_t a[4], const uint32_t b[2]) {
    asm volatile(
        "mma.sync.aligned.m16n8k8.row.col.f32.tf32.tf32.f32 "
        "{%0,%1,%2,%3}, {%4,%5,%6,%7}, {%8,%9}, {%0,%1,%2,%3};"
        : "+f"(c[0]), "+f"(c[1]), "+f"(c[2]), "+f"(c[3])
        : "r"(a[0]), "r"(a[1]), "r"(a[2]), "r"(a[3]), "r"(b[0]), "r"(b[1]));
}
__device__ __forceinline__ uint32_t smem_u32(const void* p) {
    uint32_t a;
    asm("{ .reg .u64 t; cvta.to.shared.u64 t, %1; cvt.u32.u64 %0, t; }" : "=r"(a) : "l"(p));
    return a;
}
__device__ __forceinline__ void cp16(uint32_t dst, const void* src) {
    asm volatile("cp.async.cg.shared.global [%0], [%1], 16;" :: "r"(dst), "l"(src));
}
#define CP_COMMIT() asm volatile("cp.async.commit_group;" ::: "memory")
#define CP_WAIT1()  asm volatile("cp.async.wait_group 1;" ::: "memory")
#define CP_WAIT0()  asm volatile("cp.async.wait_group 0;" ::: "memory")

// ============================================================================
// input converter: fp32 -> tf32 bits (elementwise, n % 4 == 0)
// ============================================================================
__global__ __launch_bounds__(256) void to_tf32(const float* __restrict__ in,
                                               uint32_t* __restrict__ out, int n)
{
    int i = (blockIdx.x * blockDim.x + threadIdx.x) * 4;
    if (i < n) {
        float4 v = *(const float4*)(in + i);
        *(uint4*)(out + i) = make_uint4(f2tf32(v.x), f2tf32(v.y), f2tf32(v.z), f2tf32(v.w));
    }
}

// ============================================================================
// Tensor-core TF32 GEMM (NT): C[m,n] = sum_k A[m*K+k]*B[n*K+k]
// A,B are PRE-CONVERTED tf32 bits. CTA 128x128, BK=32, 8 warps (2x4),
// cp.async 2-stage double buffer, 2 CTAs/SM.
// ============================================================================
#define GEMM_SMEM (16384 * 4)    // A buf0/1 + B buf0/1, 4096 words each = 64KB

__global__ void __launch_bounds__(256, 2) gemm_tc(
    const uint32_t* __restrict__ A, const uint32_t* __restrict__ Bm,
    float* __restrict__ C, int M, int N, int K)
{
    extern __shared__ uint32_t sm[];
    const uint32_t sbase = smem_u32(sm);

    const int tid  = threadIdx.x;
    const int lane = tid & 31;
    const int wid  = tid >> 5;
    const int wm = wid & 1;
    const int wn = wid >> 1;
    const int g = lane >> 2;
    const int t = lane & 3;
    const int bm = blockIdx.y * 128;
    const int bn = blockIdx.x * 128;

    const int lrow = tid >> 3;       // 0..31 (+p*32)
    const int lu   = tid & 7;        // 16B unit

    float acc[4][4][4];
#pragma unroll
    for (int mt = 0; mt < 4; ++mt)
#pragma unroll
        for (int nt = 0; nt < 4; ++nt)
#pragma unroll
            for (int q = 0; q < 4; ++q) acc[mt][nt][q] = 0.0f;

    auto cp_tile = [&](int k0, int buf) {
#pragma unroll
        for (int p = 0; p < 4; ++p) {
            int row = lrow + p * 32;
            int u = lu ^ (row & 7);
            cp16(sbase + (uint32_t)(buf * 4096 + row * 32 + u * 4) * 4,
                 A + (size_t)(bm + row) * K + k0 + lu * 4);
            cp16(sbase + (uint32_t)(8192 + buf * 4096 + row * 32 + u * 4) * 4,
                 Bm + (size_t)(bn + row) * K + k0 + lu * 4);
        }
    };

    cp_tile(0, 0);
    CP_COMMIT();

    const int nk = K >> 5;
    for (int kt = 0; kt < nk; ++kt) {
        const int buf = kt & 1;
        if (kt + 1 < nk) {
            cp_tile((kt + 1) << 5, buf ^ 1);
            CP_COMMIT();
            CP_WAIT1();
        } else {
            CP_WAIT0();
        }
        __syncthreads();

        const uint32_t* Asb = sm + buf * 4096;
        const uint32_t* Bsb = sm + 8192 + buf * 4096;

#pragma unroll
        for (int c8 = 0; c8 < 4; ++c8) {
            const int u0 = (2 * c8) ^ g;
            const int u1 = u0 ^ 1;

            uint32_t af[4][4];
#pragma unroll
            for (int mt = 0; mt < 4; ++mt) {
                const int r0 = wm * 64 + mt * 16 + g;
                af[mt][0] = Asb[r0 * 32 + u0 * 4 + t];
                af[mt][1] = Asb[(r0 + 8) * 32 + u0 * 4 + t];
                af[mt][2] = Asb[r0 * 32 + u1 * 4 + t];
                af[mt][3] = Asb[(r0 + 8) * 32 + u1 * 4 + t];
            }
            uint32_t bf[4][2];
#pragma unroll
            for (int nt = 0; nt < 4; ++nt) {
                const int n0 = wn * 32 + nt * 8 + g;
                bf[nt][0] = Bsb[n0 * 32 + u0 * 4 + t];
                bf[nt][1] = Bsb[n0 * 32 + u1 * 4 + t];
            }
#pragma unroll
            for (int mt = 0; mt < 4; ++mt)
#pragma unroll
                for (int nt = 0; nt < 4; ++nt)
                    mma16n8k8(acc[mt][nt], af[mt], bf[nt]);
        }
        __syncthreads();   // all warps done with buf before next cp.async overwrites buf^1's partner
    }

#pragma unroll
    for (int mt = 0; mt < 4; ++mt) {
        const int row = bm + wm * 64 + mt * 16 + g;
#pragma unroll
        for (int nt = 0; nt < 4; ++nt) {
            const int col = bn + wn * 32 + nt * 8 + 2 * t;
            *(float2*)(C + (size_t)row * N + col)       = make_float2(acc[mt][nt][0], acc[mt][nt][1]);
            *(float2*)(C + (size_t)(row + 8) * N + col) = make_float2(acc[mt][nt][2], acc[mt][nt][3]);
        }
    }
}

// ============================================================================
// RoPE + rearrange: qkv (B*T, 3C fp32) -> Q/K/V (B*H, T, hd) as tf32 bits
// ============================================================================
__global__ __launch_bounds__(256) void rope_rearrange(const float* __restrict__ qkv)
{
    int idx = blockIdx.x * blockDim.x + threadIdx.x;
    if (idx >= B_ * T_ * H_ * (HD_ / 2)) return;

    int i = idx & 31;               // pair index 0..31
    int h = (idx >> 5) & 15;
    int t = (idx >> 9) & 2047;
    int b = idx >> 20;

    const float* src = qkv + (size_t)(b * T_ + t) * QKV_N + h * HD_ + 2 * i;

    double inv = exp2(-(double)i * (13.287712379549449595 / 32.0)); // 10000^(-i/32)
    double ang = (double)t * inv;
    double ds, dc;
    sincos(ang, &ds, &dc);
    float s = (float)ds, c = (float)dc;

    float q0 = src[0],       q1 = src[1];
    float k0 = src[C_],      k1 = src[C_ + 1];
    float2 v2 = *(const float2*)(src + 2 * C_);

    size_t dst = ((size_t)(b * H_ + h) * T_ + t) * HD_ + 2 * i;
    const float qs = 0.125f;  // 1/sqrt(64)
    g_q[dst]     = f2tf32((q0 * c - q1 * s) * qs);
    g_q[dst + 1] = f2tf32((q0 * s + q1 * c) * qs);
    g_k[dst]     = f2tf32(k0 * c - k1 * s);
    g_k[dst + 1] = f2tf32(k0 * s + k1 * c);
    g_v[dst]     = f2tf32(v2.x);
    g_v[dst + 1] = f2tf32(v2.y);
}

// ============================================================================
// Tensor-core flash attention v4: Bq=128, Bk=64, hd=64. 256 threads (8 warps),
// warp = 16 q-rows. Q fragments in registers (pre-converted tf32). K/V tiles
// double-buffered via cp.async (no cvt, no staging regs). K stride 68,
// V stride 72, P staging stride 68. smem 104KB... -> 2 CTAs/SM.
// ============================================================================
#define FA_KSTR 68
#define FA_VSTR 72
#define FA_PSTR 68
#define FA_KB0  0
#define FA_KB1  (64 * FA_KSTR)                    // 4352
#define FA_VB0  (2 * 64 * FA_KSTR)                // 8704
#define FA_VB1  (FA_VB0 + 64 * FA_VSTR)           // 13312
#define FA_PW   (FA_VB1 + 64 * FA_VSTR)           // 17920
#define FLASH_SMEM ((FA_PW + 8 * 16 * FA_PSTR) * 4)   // 106496 bytes

__global__ void __launch_bounds__(256, 2) flash_tc()
{
    extern __shared__ uint32_t fsm[];
    const uint32_t sbase = smem_u32(fsm);
    uint32_t* Pw = fsm + FA_PW;

    const int bh = blockIdx.y;                // 0..63
    const int b  = bh >> 4;
    const int h  = bh & 15;
    const int q0 = blockIdx.x * 128;

    const uint32_t* Qb = g_q + (size_t)bh * T_ * HD_;
    const uint32_t* Kb = g_k + (size_t)bh * T_ * HD_;
    const uint32_t* Vb = g_v + (size_t)bh * T_ * HD_;

    const int tid  = threadIdx.x;
    const int lane = tid & 31;
    const int wid  = tid >> 5;
    const int g = lane >> 2;       // quad row
    const int t = lane & 3;        // quad col
    const int qr = wid * 16;       // warp's q-row base within tile
    uint32_t* Pme = Pw + wid * (16 * FA_PSTR);

    // ---- Q fragments in registers (loop-invariant, already tf32) ----
    uint32_t qf[8][4];
    {
        const uint32_t* qrow0 = Qb + (size_t)(q0 + qr + g) * HD_;
        const uint32_t* qrow1 = qrow0 + 8 * HD_;
#pragma unroll
        for (int c8 = 0; c8 < 8; ++c8) {
            qf[c8][0] = qrow0[c8 * 8 + t];
            qf[c8][1] = qrow1[c8 * 8 + t];
            qf[c8][2] = qrow0[c8 * 8 + t + 4];
            qf[c8][3] = qrow1[c8 * 8 + t + 4];
        }
    }

    // cp.async tile loader: 1024 16B-chunks per tile (K and V each); 4 per thread
    auto cp_kv = [&](int k0, int buf) {
        const uint32_t koff = buf ? FA_KB1 : FA_KB0;
        const uint32_t voff = buf ? FA_VB1 : FA_VB0;
#pragma unroll
        for (int p = 0; p < 4; ++p) {
            int idx = tid * 4 + p;
            int row = idx >> 4;          // 0..63
            int c4  = (idx & 15) * 4;    // word offset 0..60
            cp16(sbase + (koff + (uint32_t)row * FA_KSTR + c4) * 4,
                 Kb + (size_t)(k0 + row) * HD_ + c4);
            cp16(sbase + (voff + (uint32_t)row * FA_VSTR + c4) * 4,
                 Vb + (size_t)(k0 + row) * HD_ + c4);
        }
    };

    // online softmax state (rows qr+g and qr+g+8), O fragments
    float m0 = -3.0e38f, m1 = -3.0e38f, l0 = 0.0f, l1 = 0.0f;
    float oacc[8][4];
#pragma unroll
    for (int nt = 0; nt < 8; ++nt)
#pragma unroll
        for (int q = 0; q < 4; ++q) oacc[nt][q] = 0.0f;

    cp_kv(0, 0);
    CP_COMMIT();

    const int NT = T_ / 64;
    for (int kt = 0; kt < NT; ++kt) {
        const int buf = kt & 1;
        if (kt + 1 < NT) {
            cp_kv((kt + 1) * 64, buf ^ 1);
            CP_COMMIT();
            CP_WAIT1();
        } else {
            CP_WAIT0();
        }
        __syncthreads();

        const uint32_t* Ks = fsm + (buf ? FA_KB1 : FA_KB0);
        const uint32_t* Vs = fsm + (buf ? FA_VB1 : FA_VB0);

        // ---- S = Q K^T : warp computes 16x64 ----
        float sacc[8][4];
#pragma unroll
        for (int nt = 0; nt < 8; ++nt)
#pragma unroll
            for (int q = 0; q < 4; ++q) sacc[nt][q] = 0.0f;

#pragma unroll
        for (int c8 = 0; c8 < 8; ++c8) {
#pragma unroll
            for (int nt = 0; nt < 8; ++nt) {
                uint32_t bb[2];
                bb[0] = Ks[(nt * 8 + g) * FA_KSTR + c8 * 8 + t];
                bb[1] = Ks[(nt * 8 + g) * FA_KSTR + c8 * 8 + t + 4];
                mma16n8k8(sacc[nt], qf[c8], bb);
            }
        }

        // ---- online softmax (rows g and g+8; reduce over quad lanes t) ----
        float tm0 = -3.0e38f, tm1 = -3.0e38f;
#pragma unroll
        for (int nt = 0; nt < 8; ++nt) {
            tm0 = fmaxf(tm0, fmaxf(sacc[nt][0], sacc[nt][1]));
            tm1 = fmaxf(tm1, fmaxf(sacc[nt][2], sacc[nt][3]));
        }
#pragma unroll
        for (int off = 1; off < 4; off <<= 1) {
            tm0 = fmaxf(tm0, __shfl_xor_sync(0xffffffffu, tm0, off));
            tm1 = fmaxf(tm1, __shfl_xor_sync(0xffffffffu, tm1, off));
        }
        const float mn0 = fmaxf(m0, tm0);
        const float mn1 = fmaxf(m1, tm1);
        const float corr0 = __expf(m0 - mn0);
        const float corr1 = __expf(m1 - mn1);
        m0 = mn0; m1 = mn1;

        float rs0 = 0.0f, rs1 = 0.0f;
#pragma unroll
        for (int nt = 0; nt < 8; ++nt) {
            float p0 = __expf(sacc[nt][0] - mn0);
            float p1 = __expf(sacc[nt][1] - mn0);
            float p2 = __expf(sacc[nt][2] - mn1);
            float p3 = __expf(sacc[nt][3] - mn1);
            rs0 += p0 + p1;
            rs1 += p2 + p3;
            Pme[g * FA_PSTR + nt * 8 + 2 * t]           = f2tf32(p0);
            Pme[g * FA_PSTR + nt * 8 + 2 * t + 1]       = f2tf32(p1);
            Pme[(g + 8) * FA_PSTR + nt * 8 + 2 * t]     = f2tf32(p2);
            Pme[(g + 8) * FA_PSTR + nt * 8 + 2 * t + 1] = f2tf32(p3);
#pragma unroll
            for (int q = 0; q < 2; ++q) { oacc[nt][q] *= corr0; oacc[nt][q + 2] *= corr1; }
        }
#pragma unroll
        for (int off = 1; off < 4; off <<= 1) {
            rs0 += __shfl_xor_sync(0xffffffffu, rs0, off);
            rs1 += __shfl_xor_sync(0xffffffffu, rs1, off);
        }
        l0 = l0 * corr0 + rs0;
        l1 = l1 * corr1 + rs1;

        __syncwarp();

        // ---- O += P V : warp computes 16x64 over 64 keys ----
#pragma unroll
        for (int kk = 0; kk < 8; ++kk) {
            uint32_t a[4];
            a[0] = Pme[g * FA_PSTR + kk * 8 + t];
            a[1] = Pme[(g + 8) * FA_PSTR + kk * 8 + t];
            a[2] = Pme[g * FA_PSTR + kk * 8 + t + 4];
            a[3] = Pme[(g + 8) * FA_PSTR + kk * 8 + t + 4];
#pragma unroll
            for (int nt = 0; nt < 8; ++nt) {
                uint32_t bb[2];
                bb[0] = Vs[(kk * 8 + t) * FA_VSTR + nt * 8 + g];
                bb[1] = Vs[(kk * 8 + t + 4) * FA_VSTR + nt * 8 + g];
                mma16n8k8(oacc[nt], a, bb);
            }
        }
        __syncthreads();   // all warps done reading Ks/Vs/Pme before next overwrite
    }

    // ---- epilogue: normalize, write (B, T, C) as tf32 bits ----
    const float rl0 = 1.0f / l0;
    const float rl1 = 1.0f / l1;
    const size_t row0 = (size_t)(b * T_ + q0 + qr + g);
    const size_t row1 = row0 + 8;
#pragma unroll
    for (int nt = 0; nt < 8; ++nt) {
        const int col = h * HD_ + nt * 8 + 2 * t;
        g_y[row0 * C_ + col]     = f2tf32(oacc[nt][0] * rl0);
        g_y[row0 * C_ + col + 1] = f2tf32(oacc[nt][1] * rl0);
        g_y[row1 * C_ + col]     = f2tf32(oacc[nt][2] * rl1);
        g_y[row1 * C_ + col + 1] = f2tf32(oacc[nt][3] * rl1);
    }
}

// ============================================================================
// launch
// ============================================================================
extern "C" void kernel_launch(void* const* d_in, const int* in_sizes, int n_in,
                              void* d_out, int out_size)
{
    const float* x      = (const float*)d_in[0];
    const float* w_attn = (const float*)d_in[1];
    const float* w_proj = (const float*)d_in[2];
    float* out = (float*)d_out;

    float* qkv_ptr;  cudaGetSymbolAddress((void**)&qkv_ptr, g_qkv);
    uint32_t* y_ptr; cudaGetSymbolAddress((void**)&y_ptr,   g_y);
    uint32_t* xt;    cudaGetSymbolAddress((void**)&xt,  g_xt);
    uint32_t* wat;   cudaGetSymbolAddress((void**)&wat, g_wat);
    uint32_t* wpt;   cudaGetSymbolAddress((void**)&wpt, g_wpt);

    cudaFuncSetAttribute(flash_tc, cudaFuncAttributeMaxDynamicSharedMemorySize, FLASH_SMEM);
    cudaFuncSetAttribute(gemm_tc, cudaFuncAttributeMaxDynamicSharedMemorySize, GEMM_SMEM);

    // 0) convert inputs to tf32 bits
    {
        int nx = M_ROWS * C_;
        to_tf32<<<(nx / 4 + 255) / 256, 256>>>(x, xt, nx);
        int na = QKV_N * C_;
        to_tf32<<<(na / 4 + 255) / 256, 256>>>(w_attn, wat, na);
        int np = C_ * C_;
        to_tf32<<<(np / 4 + 255) / 256, 256>>>(w_proj, wpt, np);
    }

    // 1) QKV = x @ w_attn^T : (8192, 3072)
    gemm_tc<<<dim3(QKV_N / 128, M_ROWS / 128), 256, GEMM_SMEM>>>(
        xt, wat, qkv_ptr, M_ROWS, QKV_N, C_);

    // 2) RoPE + rearrange (-> tf32 bits)
    {
        int n = B_ * T_ * H_ * (HD_ / 2);
        rope_rearrange<<<(n + 255) / 256, 256>>>(qkv_ptr);
    }

    // 3) flash attention -> g_y (tf32 bits)
    flash_tc<<<dim3(T_ / 128, B_ * H_), 256, FLASH_SMEM>>>();

    // 4) out = y @ w_proj^T : (8192, 1024)
    gemm_tc<<<dim3(C_ / 128, M_ROWS / 128), 256, GEMM_SMEM>>>(
        y_ptr, wpt, out, M_ROWS, C_, C_);
}

// round 10
// speedup vs baseline: 2.6971x; 1.0354x over previous
#include <cuda_runtime.h>
#include <cuda_bf16.h>
#include <math.h>
#include <cstdint>

// Problem constants (fixed shapes from reference)
#define B_  4
#define T_  2048
#define C_  1024
#define H_  16
#define HD_ 64
#define M_ROWS (B_ * T_)          // 8192
#define QKV_N  (3 * C_)           // 3072

// -------- scratch (device globals; no allocation allowed) --------
__device__ float    g_qkv[(size_t)M_ROWS * QKV_N];     // fp32 (B*T, 3C)
__device__ uint32_t g_q[(size_t)B_ * H_ * T_ * HD_];   // tf32 bits, roped, scaled by 0.125*log2e
__device__ uint32_t g_k[(size_t)B_ * H_ * T_ * HD_];   // tf32 bits
__device__ uint32_t g_v[(size_t)B_ * H_ * T_ * HD_];   // tf32 bits
__device__ uint32_t g_y[(size_t)M_ROWS * C_];          // tf32 bits (B, T, C)
__device__ uint32_t g_xt[(size_t)M_ROWS * C_];         // tf32(x)
__device__ uint32_t g_wat[(size_t)QKV_N * C_];         // tf32(w_attn)
__device__ uint32_t g_wpt[(size_t)C_ * C_];            // tf32(w_proj)

// ---- tf32 / mma / cp.async helpers ----
__device__ __forceinline__ uint32_t f2tf32(float x) {
    uint32_t r; asm("cvt.rna.tf32.f32 %0, %1;" : "=r"(r) : "f"(x)); return r;
}
__device__ __forceinline__ float ex2f(float x) {
    float r; asm("ex2.approx.ftz.f32 %0, %1;" : "=f"(r) : "f"(x)); return r;
}
__device__ __forceinline__ void mma16n8k8(float c[4], const uint32_t a[4], const uint32_t b[2]) {
    asm volatile(
        "mma.sync.aligned.m16n8k8.row.col.f32.tf32.tf32.f32 "
        "{%0,%1,%2,%3}, {%4,%5,%6,%7}, {%8,%9}, {%0,%1,%2,%3};"
        : "+f"(c[0]), "+f"(c[1]), "+f"(c[2]), "+f"(c[3])
        : "r"(a[0]), "r"(a[1]), "r"(a[2]), "r"(a[3]), "r"(b[0]), "r"(b[1]));
}
__device__ __forceinline__ uint32_t smem_u32(const void* p) {
    uint32_t a;
    asm("{ .reg .u64 t; cvta.to.shared.u64 t, %1; cvt.u32.u64 %0, t; }" : "=r"(a) : "l"(p));
    return a;
}
__device__ __forceinline__ void cp16(uint32_t dst, const void* src) {
    asm volatile("cp.async.cg.shared.global [%0], [%1], 16;" :: "r"(dst), "l"(src));
}
#define CP_COMMIT() asm volatile("cp.async.commit_group;" ::: "memory")
#define CP_WAIT1()  asm volatile("cp.async.wait_group 1;" ::: "memory")
#define CP_WAIT0()  asm volatile("cp.async.wait_group 0;" ::: "memory")

// ============================================================================
// input converter: fp32 -> tf32 bits
// ============================================================================
__global__ __launch_bounds__(256) void to_tf32(const float* __restrict__ in,
                                               uint32_t* __restrict__ out, int n)
{
    int i = (blockIdx.x * blockDim.x + threadIdx.x) * 4;
    if (i < n) {
        float4 v = *(const float4*)(in + i);
        *(uint4*)(out + i) = make_uint4(f2tf32(v.x), f2tf32(v.y), f2tf32(v.z), f2tf32(v.w));
    }
}

// ============================================================================
// Tensor-core TF32 GEMM (NT): C[m,n] = sum_k A[m*K+k]*B[n*K+k]
// Pre-converted tf32 inputs. CTA 128x128, BK=32, 8 warps (2x4),
// 3-stage cp.async ring, ONE __syncthreads per K-tile, 2 CTAs/SM.
// ============================================================================
#define GEMM_SMEM (24576 * 4)    // 3 stages x (A 4096 + B 4096) words = 96KB

__global__ void __launch_bounds__(256, 2) gemm_tc(
    const uint32_t* __restrict__ A, const uint32_t* __restrict__ Bm,
    float* __restrict__ C, int M, int N, int K)
{
    extern __shared__ uint32_t sm[];
    const uint32_t sbase = smem_u32(sm);

    const int tid  = threadIdx.x;
    const int lane = tid & 31;
    const int wid  = tid >> 5;
    const int wm = wid & 1;
    const int wn = wid >> 1;
    const int g = lane >> 2;
    const int t = lane & 3;
    const int bm = blockIdx.y * 128;
    const int bn = blockIdx.x * 128;

    const int lrow = tid >> 3;       // 0..31 (+p*32)
    const int lu   = tid & 7;        // 16B unit

    float acc[4][4][4];
#pragma unroll
    for (int mt = 0; mt < 4; ++mt)
#pragma unroll
        for (int nt = 0; nt < 4; ++nt)
#pragma unroll
            for (int q = 0; q < 4; ++q) acc[mt][nt][q] = 0.0f;

    auto cp_tile = [&](int k0, int s) {
#pragma unroll
        for (int p = 0; p < 4; ++p) {
            int row = lrow + p * 32;
            int u = lu ^ (row & 7);
            cp16(sbase + (uint32_t)(s * 4096 + row * 32 + u * 4) * 4,
                 A + (size_t)(bm + row) * K + k0 + lu * 4);
            cp16(sbase + (uint32_t)(12288 + s * 4096 + row * 32 + u * 4) * 4,
                 Bm + (size_t)(bn + row) * K + k0 + lu * 4);
        }
    };

    const int nk = K >> 5;
    cp_tile(0, 0); CP_COMMIT();
    cp_tile(32, 1); CP_COMMIT();

    for (int kt = 0; kt < nk; ++kt) {
        if (kt + 1 < nk) CP_WAIT1(); else CP_WAIT0();
        __syncthreads();

        const int cs = kt % 3;
        const uint32_t* Asb = sm + cs * 4096;
        const uint32_t* Bsb = sm + 12288 + cs * 4096;

#pragma unroll
        for (int c8 = 0; c8 < 4; ++c8) {
            const int u0 = (2 * c8) ^ g;
            const int u1 = u0 ^ 1;

            uint32_t af[4][4];
#pragma unroll
            for (int mt = 0; mt < 4; ++mt) {
                const int r0 = wm * 64 + mt * 16 + g;
                af[mt][0] = Asb[r0 * 32 + u0 * 4 + t];
                af[mt][1] = Asb[(r0 + 8) * 32 + u0 * 4 + t];
                af[mt][2] = Asb[r0 * 32 + u1 * 4 + t];
                af[mt][3] = Asb[(r0 + 8) * 32 + u1 * 4 + t];
            }
            uint32_t bf[4][2];
#pragma unroll
            for (int nt = 0; nt < 4; ++nt) {
                const int n0 = wn * 32 + nt * 8 + g;
                bf[nt][0] = Bsb[n0 * 32 + u0 * 4 + t];
                bf[nt][1] = Bsb[n0 * 32 + u1 * 4 + t];
            }
#pragma unroll
            for (int mt = 0; mt < 4; ++mt)
#pragma unroll
                for (int nt = 0; nt < 4; ++nt)
                    mma16n8k8(acc[mt][nt], af[mt], bf[nt]);
        }

        if (kt + 2 < nk) {
            cp_tile((kt + 2) << 5, (kt + 2) % 3);
            CP_COMMIT();
        }
    }

#pragma unroll
    for (int mt = 0; mt < 4; ++mt) {
        const int row = bm + wm * 64 + mt * 16 + g;
#pragma unroll
        for (int nt = 0; nt < 4; ++nt) {
            const int col = bn + wn * 32 + nt * 8 + 2 * t;
            *(float2*)(C + (size_t)row * N + col)       = make_float2(acc[mt][nt][0], acc[mt][nt][1]);
            *(float2*)(C + (size_t)(row + 8) * N + col) = make_float2(acc[mt][nt][2], acc[mt][nt][3]);
        }
    }
}

// ============================================================================
// RoPE + rearrange: qkv (fp32) -> Q/K/V tf32 bits. Q scaled by 0.125*log2(e)
// so attention scores come out in log2 domain (softmax uses ex2).
// ============================================================================
__global__ __launch_bounds__(256) void rope_rearrange(const float* __restrict__ qkv)
{
    int idx = blockIdx.x * blockDim.x + threadIdx.x;
    if (idx >= B_ * T_ * H_ * (HD_ / 2)) return;

    int i = idx & 31;               // pair index 0..31
    int h = (idx >> 5) & 15;
    int t = (idx >> 9) & 2047;
    int b = idx >> 20;

    const float* src = qkv + (size_t)(b * T_ + t) * QKV_N + h * HD_ + 2 * i;

    double inv = exp2(-(double)i * (13.287712379549449595 / 32.0)); // 10000^(-i/32)
    double ang = (double)t * inv;
    double ds, dc;
    sincos(ang, &ds, &dc);
    float s = (float)ds, c = (float)dc;

    float q0 = src[0],       q1 = src[1];
    float k0 = src[C_],      k1 = src[C_ + 1];
    float2 v2 = *(const float2*)(src + 2 * C_);

    size_t dst = ((size_t)(b * H_ + h) * T_ + t) * HD_ + 2 * i;
    const float qs = 0.125f * 1.44269504088896340736f;  // 1/sqrt(64) * log2(e)
    g_q[dst]     = f2tf32((q0 * c - q1 * s) * qs);
    g_q[dst + 1] = f2tf32((q0 * s + q1 * c) * qs);
    g_k[dst]     = f2tf32(k0 * c - k1 * s);
    g_k[dst + 1] = f2tf32(k0 * s + k1 * c);
    g_v[dst]     = f2tf32(v2.x);
    g_v[dst + 1] = f2tf32(v2.y);
}

// ============================================================================
// Tensor-core flash attention v5: Bq=128, Bk=64, hd=64. 256 threads (8 warps),
// warp = 16 q-rows. Q frags in registers. K/V via 3-stage cp.async ring ->
// ONE __syncthreads per tile. P transposed C-frag->A-frag via shfl (no smem
// staging). exp2-domain softmax (single MUFU per element). smem 105KB,
// 2 CTAs/SM.
// ============================================================================
#define FA_KSTR 68
#define FA_VSTR 72
#define FA_KSZ  (64 * FA_KSTR)                    // 4352 words
#define FA_VSZ  (64 * FA_VSTR)                    // 4608 words
#define FA_VBASE (3 * FA_KSZ)                     // 13056
#define FLASH_SMEM ((3 * FA_KSZ + 3 * FA_VSZ) * 4)   // 107520 bytes

__global__ void __launch_bounds__(256, 2) flash_tc()
{
    extern __shared__ uint32_t fsm[];
    const uint32_t sbase = smem_u32(fsm);

    const int bh = blockIdx.y;                // 0..63
    const int b  = bh >> 4;
    const int h  = bh & 15;
    const int q0 = blockIdx.x * 128;

    const uint32_t* Qb = g_q + (size_t)bh * T_ * HD_;
    const uint32_t* Kb = g_k + (size_t)bh * T_ * HD_;
    const uint32_t* Vb = g_v + (size_t)bh * T_ * HD_;

    const int tid  = threadIdx.x;
    const int lane = tid & 31;
    const int wid  = tid >> 5;
    const int g = lane >> 2;       // quad row
    const int t = lane & 3;        // quad col
    const int qr = wid * 16;       // warp's q-row base within tile

    // shuffle-transpose source lanes (constant per thread)
    const int src0 = (lane & ~3) | (t >> 1);
    const int src1 = src0 + 2;
    const bool todd = (t & 1);

    // ---- Q fragments in registers (loop-invariant, tf32, log2e-scaled) ----
    uint32_t qf[8][4];
    {
        const uint32_t* qrow0 = Qb + (size_t)(q0 + qr + g) * HD_;
        const uint32_t* qrow1 = qrow0 + 8 * HD_;
#pragma unroll
        for (int c8 = 0; c8 < 8; ++c8) {
            qf[c8][0] = qrow0[c8 * 8 + t];
            qf[c8][1] = qrow1[c8 * 8 + t];
            qf[c8][2] = qrow0[c8 * 8 + t + 4];
            qf[c8][3] = qrow1[c8 * 8 + t + 4];
        }
    }

    // cp.async tile loader: K tile (stride 68) + V tile (stride 72)
    auto cp_kv = [&](int k0, int s) {
        const uint32_t koff = (uint32_t)s * FA_KSZ;
        const uint32_t voff = FA_VBASE + (uint32_t)s * FA_VSZ;
#pragma unroll
        for (int p = 0; p < 4; ++p) {
            int idx = tid * 4 + p;
            int row = idx >> 4;          // 0..63
            int c4  = (idx & 15) * 4;    // word offset 0..60
            cp16(sbase + (koff + (uint32_t)row * FA_KSTR + c4) * 4,
                 Kb + (size_t)(k0 + row) * HD_ + c4);
            cp16(sbase + (voff + (uint32_t)row * FA_VSTR + c4) * 4,
                 Vb + (size_t)(k0 + row) * HD_ + c4);
        }
    };

    // online softmax state (rows qr+g, qr+g+8) in log2 domain; O fragments
    float m0 = -3.0e38f, m1 = -3.0e38f, l0 = 0.0f, l1 = 0.0f;
    float oacc[8][4];
#pragma unroll
    for (int nt = 0; nt < 8; ++nt)
#pragma unroll
        for (int q = 0; q < 4; ++q) oacc[nt][q] = 0.0f;

    const int NT = T_ / 64;
    cp_kv(0, 0);  CP_COMMIT();
    cp_kv(64, 1); CP_COMMIT();

    for (int kt = 0; kt < NT; ++kt) {
        if (kt + 1 < NT) CP_WAIT1(); else CP_WAIT0();
        __syncthreads();

        const int cs = kt % 3;
        const uint32_t* Ks = fsm + cs * FA_KSZ;
        const uint32_t* Vs = fsm + FA_VBASE + cs * FA_VSZ;

        // ---- S = Q K^T (log2 domain): warp computes 16x64 ----
        float sacc[8][4];
#pragma unroll
        for (int nt = 0; nt < 8; ++nt)
#pragma unroll
            for (int q = 0; q < 4; ++q) sacc[nt][q] = 0.0f;

#pragma unroll
        for (int c8 = 0; c8 < 8; ++c8) {
#pragma unroll
            for (int nt = 0; nt < 8; ++nt) {
                uint32_t bb[2];
                bb[0] = Ks[(nt * 8 + g) * FA_KSTR + c8 * 8 + t];
                bb[1] = Ks[(nt * 8 + g) * FA_KSTR + c8 * 8 + t + 4];
                mma16n8k8(sacc[nt], qf[c8], bb);
            }
        }

        // ---- online softmax (exp2 domain; reduce over quad lanes) ----
        float tm0 = -3.0e38f, tm1 = -3.0e38f;
#pragma unroll
        for (int nt = 0; nt < 8; ++nt) {
            tm0 = fmaxf(tm0, fmaxf(sacc[nt][0], sacc[nt][1]));
            tm1 = fmaxf(tm1, fmaxf(sacc[nt][2], sacc[nt][3]));
        }
#pragma unroll
        for (int off = 1; off < 4; off <<= 1) {
            tm0 = fmaxf(tm0, __shfl_xor_sync(0xffffffffu, tm0, off));
            tm1 = fmaxf(tm1, __shfl_xor_sync(0xffffffffu, tm1, off));
        }
        const float mn0 = fmaxf(m0, tm0);
        const float mn1 = fmaxf(m1, tm1);
        const float corr0 = ex2f(m0 - mn0);
        const float corr1 = ex2f(m1 - mn1);
        m0 = mn0; m1 = mn1;

        float rs0 = 0.0f, rs1 = 0.0f;
#pragma unroll
        for (int nt = 0; nt < 8; ++nt) {
            float p0 = ex2f(sacc[nt][0] - mn0);
            float p1 = ex2f(sacc[nt][1] - mn0);
            float p2 = ex2f(sacc[nt][2] - mn1);
            float p3 = ex2f(sacc[nt][3] - mn1);
            sacc[nt][0] = p0; sacc[nt][1] = p1; sacc[nt][2] = p2; sacc[nt][3] = p3;
            rs0 += p0 + p1;
            rs1 += p2 + p3;
#pragma unroll
            for (int q = 0; q < 2; ++q) { oacc[nt][q] *= corr0; oacc[nt][q + 2] *= corr1; }
        }
#pragma unroll
        for (int off = 1; off < 4; off <<= 1) {
            rs0 += __shfl_xor_sync(0xffffffffu, rs0, off);
            rs1 += __shfl_xor_sync(0xffffffffu, rs1, off);
        }
        l0 = l0 * corr0 + rs0;
        l1 = l1 * corr1 + rs1;

        // ---- O += P V : P A-frags built by shfl transpose of C-frags ----
        // C-frag: lane (g,t') holds P[g][2t'], P[g][2t'+1], P[g+8][2t'], P[g+8][2t'+1]
        // A-frag needs lane (g,t): P[g][t], P[g+8][t], P[g][t+4], P[g+8][t+4]
        // col j lives in lane (g, j>>1), reg (j&1) / (2+(j&1)).
#pragma unroll
        for (int kk = 0; kk < 8; ++kk) {
            float x0 = __shfl_sync(0xffffffffu, sacc[kk][0], src0);
            float x1 = __shfl_sync(0xffffffffu, sacc[kk][1], src0);
            float x2 = __shfl_sync(0xffffffffu, sacc[kk][2], src0);
            float x3 = __shfl_sync(0xffffffffu, sacc[kk][3], src0);
            float y0 = __shfl_sync(0xffffffffu, sacc[kk][0], src1);
            float y1 = __shfl_sync(0xffffffffu, sacc[kk][1], src1);
            float y2 = __shfl_sync(0xffffffffu, sacc[kk][2], src1);
            float y3 = __shfl_sync(0xffffffffu, sacc[kk][3], src1);
            uint32_t a[4];
            a[0] = f2tf32(todd ? x1 : x0);
            a[1] = f2tf32(todd ? x3 : x2);
            a[2] = f2tf32(todd ? y1 : y0);
            a[3] = f2tf32(todd ? y3 : y2);
#pragma unroll
            for (int nt = 0; nt < 8; ++nt) {
                uint32_t bb[2];
                bb[0] = Vs[(kk * 8 + t) * FA_VSTR + nt * 8 + g];
                bb[1] = Vs[(kk * 8 + t + 4) * FA_VSTR + nt * 8 + g];
                mma16n8k8(oacc[nt], a, bb);
            }
        }

        if (kt + 2 < NT) {
            cp_kv((kt + 2) * 64, (kt + 2) % 3);
            CP_COMMIT();
        }
    }

    // ---- epilogue: normalize, write (B, T, C) as tf32 bits ----
    const float rl0 = 1.0f / l0;
    const float rl1 = 1.0f / l1;
    const size_t row0 = (size_t)(b * T_ + q0 + qr + g);
    const size_t row1 = row0 + 8;
#pragma unroll
    for (int nt = 0; nt < 8; ++nt) {
        const int col = h * HD_ + nt * 8 + 2 * t;
        g_y[row0 * C_ + col]     = f2tf32(oacc[nt][0] * rl0);
        g_y[row0 * C_ + col + 1] = f2tf32(oacc[nt][1] * rl0);
        g_y[row1 * C_ + col]     = f2tf32(oacc[nt][2] * rl1);
        g_y[row1 * C_ + col + 1] = f2tf32(oacc[nt][3] * rl1);
    }
}

// ============================================================================
// launch
// ============================================================================
extern "C" void kernel_launch(void* const* d_in, const int* in_sizes, int n_in,
                              void* d_out, int out_size)
{
    const float* x      = (const float*)d_in[0];
    const float* w_attn = (const float*)d_in[1];
    const float* w_proj = (const float*)d_in[2];
    float* out = (float*)d_out;

    float* qkv_ptr;  cudaGetSymbolAddress((void**)&qkv_ptr, g_qkv);
    uint32_t* y_ptr; cudaGetSymbolAddress((void**)&y_ptr,   g_y);
    uint32_t* xt;    cudaGetSymbolAddress((void**)&xt,  g_xt);
    uint32_t* wat;   cudaGetSymbolAddress((void**)&wat, g_wat);
    uint32_t* wpt;   cudaGetSymbolAddress((void**)&wpt, g_wpt);

    cudaFuncSetAttribute(flash_tc, cudaFuncAttributeMaxDynamicSharedMemorySize, FLASH_SMEM);
    cudaFuncSetAttribute(gemm_tc, cudaFuncAttributeMaxDynamicSharedMemorySize, GEMM_SMEM);

    // 0) convert inputs to tf32 bits
    {
        int nx = M_ROWS * C_;
        to_tf32<<<(nx / 4 + 255) / 256, 256>>>(x, xt, nx);
        int na = QKV_N * C_;
        to_tf32<<<(na / 4 + 255) / 256, 256>>>(w_attn, wat, na);
        int np = C_ * C_;
        to_tf32<<<(np / 4 + 255) / 256, 256>>>(w_proj, wpt, np);
    }

    // 1) QKV = x @ w_attn^T : (8192, 3072)
    gemm_tc<<<dim3(QKV_N / 128, M_ROWS / 128), 256, GEMM_SMEM>>>(
        xt, wat, qkv_ptr, M_ROWS, QKV_N, C_);

    // 2) RoPE + rearrange (-> tf32 bits; Q scaled by 0.125*log2e)
    {
        int n = B_ * T_ * H_ * (HD_ / 2);
        rope_rearrange<<<(n + 255) / 256, 256>>>(qkv_ptr);
    }

    // 3) flash attention -> g_y (tf32 bits)
    flash_tc<<<dim3(T_ / 128, B_ * H_), 256, FLASH_SMEM>>>();

    // 4) out = y @ w_proj^T : (8192, 1024)
    gemm_tc<<<dim3(C_ / 128, M_ROWS / 128), 256, GEMM_SMEM>>>(
        y_ptr, wpt, out, M_ROWS, C_, C_);
}

// round 11
// speedup vs baseline: 3.5344x; 1.3104x over previous
#include <cuda_runtime.h>
#include <cuda_bf16.h>
#include <math.h>
#include <cstdint>

// Problem constants (fixed shapes from reference)
#define B_  4
#define T_  2048
#define C_  1024
#define H_  16
#define HD_ 64
#define M_ROWS (B_ * T_)          // 8192
#define QKV_N  (3 * C_)           // 3072

// -------- scratch (device globals; no allocation allowed) --------
__device__ float    g_qkv[(size_t)M_ROWS * QKV_N];     // fp32 (B*T, 3C)
__device__ uint32_t g_q[(size_t)B_ * H_ * T_ * HD_];   // tf32 bits, roped, scaled by 0.125*log2e
__device__ uint32_t g_k[(size_t)B_ * H_ * T_ * HD_];   // tf32 bits
__device__ uint32_t g_v[(size_t)B_ * H_ * T_ * HD_];   // tf32 bits
__device__ uint32_t g_y[(size_t)M_ROWS * C_];          // tf32 bits (B, T, C)
__device__ uint32_t g_xt[(size_t)M_ROWS * C_];         // tf32(x)
__device__ uint32_t g_wat[(size_t)QKV_N * C_];         // tf32(w_attn)
__device__ uint32_t g_wpt[(size_t)C_ * C_];            // tf32(w_proj)
__device__ float2   g_rt[(size_t)T_ * 32];             // rope cos/sin table

// ---- tf32 / mma / cp.async helpers ----
__device__ __forceinline__ uint32_t f2tf32(float x) {
    uint32_t r; asm("cvt.rna.tf32.f32 %0, %1;" : "=r"(r) : "f"(x)); return r;
}
__device__ __forceinline__ float ex2f(float x) {
    float r; asm("ex2.approx.ftz.f32 %0, %1;" : "=f"(r) : "f"(x)); return r;
}
__device__ __forceinline__ void mma16n8k8(float c[4], const uint32_t a[4], const uint32_t b[2]) {
    asm volatile(
        "mma.sync.aligned.m16n8k8.row.col.f32.tf32.tf32.f32 "
        "{%0,%1,%2,%3}, {%4,%5,%6,%7}, {%8,%9}, {%0,%1,%2,%3};"
        : "+f"(c[0]), "+f"(c[1]), "+f"(c[2]), "+f"(c[3])
        : "r"(a[0]), "r"(a[1]), "r"(a[2]), "r"(a[3]), "r"(b[0]), "r"(b[1]));
}
__device__ __forceinline__ uint32_t smem_u32(const void* p) {
    uint32_t a;
    asm("{ .reg .u64 t; cvta.to.shared.u64 t, %1; cvt.u32.u64 %0, t; }" : "=r"(a) : "l"(p));
    return a;
}
__device__ __forceinline__ void cp16(uint32_t dst, const void* src) {
    asm volatile("cp.async.cg.shared.global [%0], [%1], 16;" :: "r"(dst), "l"(src));
}
#define CP_COMMIT() asm volatile("cp.async.commit_group;" ::: "memory")
#define CP_WAIT1()  asm volatile("cp.async.wait_group 1;" ::: "memory")
#define CP_WAIT0()  asm volatile("cp.async.wait_group 0;" ::: "memory")

// ============================================================================
// input converter: fp32 -> tf32 bits
// ============================================================================
__global__ __launch_bounds__(256) void to_tf32(const float* __restrict__ in,
                                               uint32_t* __restrict__ out, int n)
{
    int i = (blockIdx.x * blockDim.x + threadIdx.x) * 4;
    if (i < n) {
        float4 v = *(const float4*)(in + i);
        *(uint4*)(out + i) = make_uint4(f2tf32(v.x), f2tf32(v.y), f2tf32(v.z), f2tf32(v.w));
    }
}

// ============================================================================
// Tensor-core TF32 GEMM (NT) — unchanged from Round 10 passing version.
// ============================================================================
#define GEMM_SMEM (24576 * 4)    // 3 stages x (A 4096 + B 4096) words = 96KB

__global__ void __launch_bounds__(256, 2) gemm_tc(
    const uint32_t* __restrict__ A, const uint32_t* __restrict__ Bm,
    float* __restrict__ C, int M, int N, int K)
{
    extern __shared__ uint32_t sm[];
    const uint32_t sbase = smem_u32(sm);

    const int tid  = threadIdx.x;
    const int lane = tid & 31;
    const int wid  = tid >> 5;
    const int wm = wid & 1;
    const int wn = wid >> 1;
    const int g = lane >> 2;
    const int t = lane & 3;
    const int bm = blockIdx.y * 128;
    const int bn = blockIdx.x * 128;

    const int lrow = tid >> 3;       // 0..31 (+p*32)
    const int lu   = tid & 7;        // 16B unit

    float acc[4][4][4];
#pragma unroll
    for (int mt = 0; mt < 4; ++mt)
#pragma unroll
        for (int nt = 0; nt < 4; ++nt)
#pragma unroll
            for (int q = 0; q < 4; ++q) acc[mt][nt][q] = 0.0f;

    auto cp_tile = [&](int k0, int s) {
#pragma unroll
        for (int p = 0; p < 4; ++p) {
            int row = lrow + p * 32;
            int u = lu ^ (row & 7);
            cp16(sbase + (uint32_t)(s * 4096 + row * 32 + u * 4) * 4,
                 A + (size_t)(bm + row) * K + k0 + lu * 4);
            cp16(sbase + (uint32_t)(12288 + s * 4096 + row * 32 + u * 4) * 4,
                 Bm + (size_t)(bn + row) * K + k0 + lu * 4);
        }
    };

    const int nk = K >> 5;
    cp_tile(0, 0); CP_COMMIT();
    cp_tile(32, 1); CP_COMMIT();

    for (int kt = 0; kt < nk; ++kt) {
        if (kt + 1 < nk) CP_WAIT1(); else CP_WAIT0();
        __syncthreads();

        const int cs = kt % 3;
        const uint32_t* Asb = sm + cs * 4096;
        const uint32_t* Bsb = sm + 12288 + cs * 4096;

#pragma unroll
        for (int c8 = 0; c8 < 4; ++c8) {
            const int u0 = (2 * c8) ^ g;
            const int u1 = u0 ^ 1;

            uint32_t af[4][4];
#pragma unroll
            for (int mt = 0; mt < 4; ++mt) {
                const int r0 = wm * 64 + mt * 16 + g;
                af[mt][0] = Asb[r0 * 32 + u0 * 4 + t];
                af[mt][1] = Asb[(r0 + 8) * 32 + u0 * 4 + t];
                af[mt][2] = Asb[r0 * 32 + u1 * 4 + t];
                af[mt][3] = Asb[(r0 + 8) * 32 + u1 * 4 + t];
            }
            uint32_t bf[4][2];
#pragma unroll
            for (int nt = 0; nt < 4; ++nt) {
                const int n0 = wn * 32 + nt * 8 + g;
                bf[nt][0] = Bsb[n0 * 32 + u0 * 4 + t];
                bf[nt][1] = Bsb[n0 * 32 + u1 * 4 + t];
            }
#pragma unroll
            for (int mt = 0; mt < 4; ++mt)
#pragma unroll
                for (int nt = 0; nt < 4; ++nt)
                    mma16n8k8(acc[mt][nt], af[mt], bf[nt]);
        }

        if (kt + 2 < nk) {
            cp_tile((kt + 2) << 5, (kt + 2) % 3);
            CP_COMMIT();
        }
    }

#pragma unroll
    for (int mt = 0; mt < 4; ++mt) {
        const int row = bm + wm * 64 + mt * 16 + g;
#pragma unroll
        for (int nt = 0; nt < 4; ++nt) {
            const int col = bn + wn * 32 + nt * 8 + 2 * t;
            *(float2*)(C + (size_t)row * N + col)       = make_float2(acc[mt][nt][0], acc[mt][nt][1]);
            *(float2*)(C + (size_t)(row + 8) * N + col) = make_float2(acc[mt][nt][2], acc[mt][nt][3]);
        }
    }
}

// ============================================================================
// RoPE table: cos/sin for (t, i) computed once per launch (fp64 accurate)
// ============================================================================
__global__ __launch_bounds__(256) void rope_tab()
{
    int idx = blockIdx.x * blockDim.x + threadIdx.x;
    if (idx >= T_ * 32) return;
    int i = idx & 31;
    int t = idx >> 5;
    double inv = exp2(-(double)i * (13.287712379549449595 / 32.0)); // 10000^(-i/32)
    double ds, dc;
    sincos((double)t * inv, &ds, &dc);
    g_rt[idx] = make_float2((float)dc, (float)ds);
}

// ============================================================================
// RoPE + rearrange: qkv (fp32) -> Q/K/V tf32 bits. Q scaled by 0.125*log2(e).
// ============================================================================
__global__ __launch_bounds__(256) void rope_rearrange(const float* __restrict__ qkv)
{
    int idx = blockIdx.x * blockDim.x + threadIdx.x;
    if (idx >= B_ * T_ * H_ * (HD_ / 2)) return;

    int i = idx & 31;               // pair index 0..31
    int h = (idx >> 5) & 15;
    int t = (idx >> 9) & 2047;
    int b = idx >> 20;

    const float* src = qkv + (size_t)(b * T_ + t) * QKV_N + h * HD_ + 2 * i;

    float2 cs = g_rt[t * 32 + i];
    float c = cs.x, s = cs.y;

    float q0 = src[0],       q1 = src[1];
    float k0 = src[C_],      k1 = src[C_ + 1];
    float2 v2 = *(const float2*)(src + 2 * C_);

    size_t dst = ((size_t)(b * H_ + h) * T_ + t) * HD_ + 2 * i;
    const float qs = 0.125f * 1.44269504088896340736f;  // 1/sqrt(64) * log2(e)
    g_q[dst]     = f2tf32((q0 * c - q1 * s) * qs);
    g_q[dst + 1] = f2tf32((q0 * s + q1 * c) * qs);
    g_k[dst]     = f2tf32(k0 * c - k1 * s);
    g_k[dst + 1] = f2tf32(k0 * s + k1 * c);
    g_v[dst]     = f2tf32(v2.x);
    g_v[dst + 1] = f2tf32(v2.y);
}

// ============================================================================
// Tensor-core flash attention v6: Bq=128, Bk=64, hd=64. 256 threads (8 warps),
// warp = 16 q-rows. Q frags in registers. K/V via 2-stage cp.async ring with
// prefetch issued AFTER the single per-tile sync (WAR-safe). P transpose via
// shfl. exp2 softmax. Per-lane deferred l-sum (quad-reduced in epilogue).
// smem 70KB -> 2 CTAs/SM.
// ============================================================================
#define FA_KSTR 68
#define FA_VSTR 72
#define FA_KSZ  (64 * FA_KSTR)                    // 4352 words
#define FA_VSZ  (64 * FA_VSTR)                    // 4608 words
#define FA_STG  (FA_KSZ + FA_VSZ)                 // 8960 words per stage
#define FLASH_SMEM (2 * FA_STG * 4)               // 71680 bytes

__global__ void __launch_bounds__(256, 2) flash_tc()
{
    extern __shared__ uint32_t fsm[];
    const uint32_t sbase = smem_u32(fsm);

    const int bh = blockIdx.y;                // 0..63
    const int b  = bh >> 4;
    const int h  = bh & 15;
    const int q0 = blockIdx.x * 128;

    const uint32_t* Qb = g_q + (size_t)bh * T_ * HD_;
    const uint32_t* Kb = g_k + (size_t)bh * T_ * HD_;
    const uint32_t* Vb = g_v + (size_t)bh * T_ * HD_;

    const int tid  = threadIdx.x;
    const int lane = tid & 31;
    const int wid  = tid >> 5;
    const int g = lane >> 2;       // quad row
    const int t = lane & 3;        // quad col
    const int qr = wid * 16;       // warp's q-row base within tile

    // shuffle-transpose source lanes (constant per thread)
    const int src0 = (lane & ~3) | (t >> 1);
    const int src1 = src0 + 2;
    const bool todd = (t & 1);

    // ---- Q fragments in registers (loop-invariant, tf32, log2e-scaled) ----
    uint32_t qf[8][4];
    {
        const uint32_t* qrow0 = Qb + (size_t)(q0 + qr + g) * HD_;
        const uint32_t* qrow1 = qrow0 + 8 * HD_;
#pragma unroll
        for (int c8 = 0; c8 < 8; ++c8) {
            qf[c8][0] = qrow0[c8 * 8 + t];
            qf[c8][1] = qrow1[c8 * 8 + t];
            qf[c8][2] = qrow0[c8 * 8 + t + 4];
            qf[c8][3] = qrow1[c8 * 8 + t + 4];
        }
    }

    // cp.async tile loader: K tile (stride 68) + V tile (stride 72)
    auto cp_kv = [&](int k0, int s) {
        const uint32_t koff = (uint32_t)s * FA_STG;
        const uint32_t voff = koff + FA_KSZ;
#pragma unroll
        for (int p = 0; p < 4; ++p) {
            int idx = tid * 4 + p;
            int row = idx >> 4;          // 0..63
            int c4  = (idx & 15) * 4;    // word offset 0..60
            cp16(sbase + (koff + (uint32_t)row * FA_KSTR + c4) * 4,
                 Kb + (size_t)(k0 + row) * HD_ + c4);
            cp16(sbase + (voff + (uint32_t)row * FA_VSTR + c4) * 4,
                 Vb + (size_t)(k0 + row) * HD_ + c4);
        }
    };

    // online softmax state (rows qr+g, qr+g+8) in log2 domain.
    // l0/l1 are PER-LANE partial sums (quad-reduced at the end).
    float m0 = -3.0e38f, m1 = -3.0e38f, l0 = 0.0f, l1 = 0.0f;
    float oacc[8][4];
#pragma unroll
    for (int nt = 0; nt < 8; ++nt)
#pragma unroll
        for (int q = 0; q < 4; ++q) oacc[nt][q] = 0.0f;

    const int NT = T_ / 64;
    cp_kv(0, 0); CP_COMMIT();

    for (int kt = 0; kt < NT; ++kt) {
        CP_WAIT0();
        __syncthreads();
        if (kt + 1 < NT) {
            cp_kv((kt + 1) * 64, (kt + 1) & 1);
            CP_COMMIT();
        }

        const int cs = kt & 1;
        const uint32_t* Ks = fsm + cs * FA_STG;
        const uint32_t* Vs = fsm + cs * FA_STG + FA_KSZ;

        // ---- S = Q K^T (log2 domain): warp computes 16x64 ----
        float sacc[8][4];
#pragma unroll
        for (int nt = 0; nt < 8; ++nt)
#pragma unroll
            for (int q = 0; q < 4; ++q) sacc[nt][q] = 0.0f;

#pragma unroll
        for (int c8 = 0; c8 < 8; ++c8) {
#pragma unroll
            for (int nt = 0; nt < 8; ++nt) {
                uint32_t bb[2];
                bb[0] = Ks[(nt * 8 + g) * FA_KSTR + c8 * 8 + t];
                bb[1] = Ks[(nt * 8 + g) * FA_KSTR + c8 * 8 + t + 4];
                mma16n8k8(sacc[nt], qf[c8], bb);
            }
        }

        // ---- online softmax (exp2 domain; only MAX needs quad reduce) ----
        float tm0 = -3.0e38f, tm1 = -3.0e38f;
#pragma unroll
        for (int nt = 0; nt < 8; ++nt) {
            tm0 = fmaxf(tm0, fmaxf(sacc[nt][0], sacc[nt][1]));
            tm1 = fmaxf(tm1, fmaxf(sacc[nt][2], sacc[nt][3]));
        }
#pragma unroll
        for (int off = 1; off < 4; off <<= 1) {
            tm0 = fmaxf(tm0, __shfl_xor_sync(0xffffffffu, tm0, off));
            tm1 = fmaxf(tm1, __shfl_xor_sync(0xffffffffu, tm1, off));
        }
        const float mn0 = fmaxf(m0, tm0);
        const float mn1 = fmaxf(m1, tm1);
        const float corr0 = ex2f(m0 - mn0);
        const float corr1 = ex2f(m1 - mn1);
        m0 = mn0; m1 = mn1;

        float rs0 = 0.0f, rs1 = 0.0f;
#pragma unroll
        for (int nt = 0; nt < 8; ++nt) {
            float p0 = ex2f(sacc[nt][0] - mn0);
            float p1 = ex2f(sacc[nt][1] - mn0);
            float p2 = ex2f(sacc[nt][2] - mn1);
            float p3 = ex2f(sacc[nt][3] - mn1);
            sacc[nt][0] = p0; sacc[nt][1] = p1; sacc[nt][2] = p2; sacc[nt][3] = p3;
            rs0 += p0 + p1;
            rs1 += p2 + p3;
#pragma unroll
            for (int q = 0; q < 2; ++q) { oacc[nt][q] *= corr0; oacc[nt][q + 2] *= corr1; }
        }
        l0 = l0 * corr0 + rs0;     // per-lane partial (no shfl)
        l1 = l1 * corr1 + rs1;

        // ---- O += P V : P A-frags built by shfl transpose of C-frags ----
#pragma unroll
        for (int kk = 0; kk < 8; ++kk) {
            float x0 = __shfl_sync(0xffffffffu, sacc[kk][0], src0);
            float x1 = __shfl_sync(0xffffffffu, sacc[kk][1], src0);
            float x2 = __shfl_sync(0xffffffffu, sacc[kk][2], src0);
            float x3 = __shfl_sync(0xffffffffu, sacc[kk][3], src0);
            float y0 = __shfl_sync(0xffffffffu, sacc[kk][0], src1);
            float y1 = __shfl_sync(0xffffffffu, sacc[kk][1], src1);
            float y2 = __shfl_sync(0xffffffffu, sacc[kk][2], src1);
            float y3 = __shfl_sync(0xffffffffu, sacc[kk][3], src1);
            uint32_t a[4];
            a[0] = f2tf32(todd ? x1 : x0);
            a[1] = f2tf32(todd ? x3 : x2);
            a[2] = f2tf32(todd ? y1 : y0);
            a[3] = f2tf32(todd ? y3 : y2);
#pragma unroll
            for (int nt = 0; nt < 8; ++nt) {
                uint32_t bb[2];
                bb[0] = Vs[(kk * 8 + t) * FA_VSTR + nt * 8 + g];
                bb[1] = Vs[(kk * 8 + t + 4) * FA_VSTR + nt * 8 + g];
                mma16n8k8(oacc[nt], a, bb);
            }
        }
    }

    // ---- epilogue: reduce l across quad, normalize, write tf32 bits ----
#pragma unroll
    for (int off = 1; off < 4; off <<= 1) {
        l0 += __shfl_xor_sync(0xffffffffu, l0, off);
        l1 += __shfl_xor_sync(0xffffffffu, l1, off);
    }
    const float rl0 = 1.0f / l0;
    const float rl1 = 1.0f / l1;
    const size_t row0 = (size_t)(b * T_ + q0 + qr + g);
    const size_t row1 = row0 + 8;
#pragma unroll
    for (int nt = 0; nt < 8; ++nt) {
        const int col = h * HD_ + nt * 8 + 2 * t;
        *(uint2*)(g_y + row0 * C_ + col) =
            make_uint2(f2tf32(oacc[nt][0] * rl0), f2tf32(oacc[nt][1] * rl0));
        *(uint2*)(g_y + row1 * C_ + col) =
            make_uint2(f2tf32(oacc[nt][2] * rl1), f2tf32(oacc[nt][3] * rl1));
    }
}

// ============================================================================
// launch
// ============================================================================
extern "C" void kernel_launch(void* const* d_in, const int* in_sizes, int n_in,
                              void* d_out, int out_size)
{
    const float* x      = (const float*)d_in[0];
    const float* w_attn = (const float*)d_in[1];
    const float* w_proj = (const float*)d_in[2];
    float* out = (float*)d_out;

    float* qkv_ptr;  cudaGetSymbolAddress((void**)&qkv_ptr, g_qkv);
    uint32_t* y_ptr; cudaGetSymbolAddress((void**)&y_ptr,   g_y);
    uint32_t* xt;    cudaGetSymbolAddress((void**)&xt,  g_xt);
    uint32_t* wat;   cudaGetSymbolAddress((void**)&wat, g_wat);
    uint32_t* wpt;   cudaGetSymbolAddress((void**)&wpt, g_wpt);

    cudaFuncSetAttribute(flash_tc, cudaFuncAttributeMaxDynamicSharedMemorySize, FLASH_SMEM);
    cudaFuncSetAttribute(gemm_tc, cudaFuncAttributeMaxDynamicSharedMemorySize, GEMM_SMEM);

    // 0) convert inputs to tf32 bits; build rope table
    {
        int nx = M_ROWS * C_;
        to_tf32<<<(nx / 4 + 255) / 256, 256>>>(x, xt, nx);
        int na = QKV_N * C_;
        to_tf32<<<(na / 4 + 255) / 256, 256>>>(w_attn, wat, na);
        int np = C_ * C_;
        to_tf32<<<(np / 4 + 255) / 256, 256>>>(w_proj, wpt, np);
        rope_tab<<<(T_ * 32 + 255) / 256, 256>>>();
    }

    // 1) QKV = x @ w_attn^T : (8192, 3072)
    gemm_tc<<<dim3(QKV_N / 128, M_ROWS / 128), 256, GEMM_SMEM>>>(
        xt, wat, qkv_ptr, M_ROWS, QKV_N, C_);

    // 2) RoPE + rearrange (-> tf32 bits; Q scaled by 0.125*log2e)
    {
        int n = B_ * T_ * H_ * (HD_ / 2);
        rope_rearrange<<<(n + 255) / 256, 256>>>(qkv_ptr);
    }

    // 3) flash attention -> g_y (tf32 bits)
    flash_tc<<<dim3(T_ / 128, B_ * H_), 256, FLASH_SMEM>>>();

    // 4) out = y @ w_proj^T : (8192, 1024)
    gemm_tc<<<dim3(C_ / 128, M_ROWS / 128), 256, GEMM_SMEM>>>(
        y_ptr, wpt, out, M_ROWS, C_, C_);
}